// round 13
// baseline (speedup 1.0000x reference)
#include <cuda_runtime.h>
#include <cuda_bf16.h>
#include <cstdint>

// ================= scratch (device globals; allocation-free) ==================
#define MROWS 4096
#define CDIM  1024

__device__ float g_t  [MROWS * 16];
__device__ unsigned short g_h2  [(size_t)2 * MROWS * CDIM];
__device__ unsigned short g_o2  [(size_t)2 * MROWS * CDIM];
__device__ unsigned short g_f2  [(size_t)2 * MROWS * CDIM];
__device__ unsigned short g_qkv2[(size_t)2 * MROWS * 3 * CDIM];
__device__ unsigned short g_kv2 [(size_t)2 * MROWS * 2 * CDIM];
__device__ unsigned short g_mlp2[(size_t)2 * MROWS * 4 * CDIM];
__device__ unsigned short g_wqkv2 [(size_t)2 * 3 * CDIM * CDIM];
__device__ unsigned short g_wsap2 [(size_t)2 * CDIM * CDIM];
__device__ unsigned short g_wcaq2 [(size_t)2 * CDIM * CDIM];
__device__ unsigned short g_wcakv2[(size_t)2 * 2 * CDIM * CDIM];
__device__ unsigned short g_wcap2 [(size_t)2 * CDIM * CDIM];
__device__ unsigned short g_wfc2  [(size_t)2 * 4 * CDIM * CDIM];
__device__ unsigned short g_wpr2  [(size_t)2 * CDIM * 4 * CDIM];

static const int F_LORA = 1, F_GELU = 2, F_RES = 4, F_PACK = 8;

// ================= helpers ====================================================
__device__ __forceinline__ uint32_t smem_u32(const void* p) {
    uint32_t a;
    asm("{ .reg .u64 t; cvta.to.shared.u64 t, %1; cvt.u32.u64 %0, t; }"
        : "=r"(a) : "l"(p));
    return a;
}
__device__ __forceinline__ void ldmatrix_x4(uint32_t* r, uint32_t addr) {
    asm volatile("ldmatrix.sync.aligned.m8n8.x4.shared.b16 {%0,%1,%2,%3}, [%4];"
        : "=r"(r[0]), "=r"(r[1]), "=r"(r[2]), "=r"(r[3]) : "r"(addr));
}
__device__ __forceinline__ void ldmatrix_x4_t(uint32_t* r, uint32_t addr) {
    asm volatile("ldmatrix.sync.aligned.m8n8.x4.trans.shared.b16 {%0,%1,%2,%3}, [%4];"
        : "=r"(r[0]), "=r"(r[1]), "=r"(r[2]), "=r"(r[3]) : "r"(addr));
}
__device__ __forceinline__ void mma16816(float* c, const uint32_t* a,
                                         uint32_t b0, uint32_t b1) {
    asm volatile("mma.sync.aligned.m16n8k16.row.col.f32.bf16.bf16.f32 "
        "{%0,%1,%2,%3}, {%4,%5,%6,%7}, {%8,%9}, {%0,%1,%2,%3};"
        : "+f"(c[0]), "+f"(c[1]), "+f"(c[2]), "+f"(c[3])
        : "r"(a[0]), "r"(a[1]), "r"(a[2]), "r"(a[3]), "r"(b0), "r"(b1));
}
__device__ __forceinline__ uint32_t pack2hi(float a, float b) {
    return (uint32_t)__bfloat16_as_ushort(__float2bfloat16(a))
         | ((uint32_t)__bfloat16_as_ushort(__float2bfloat16(b)) << 16);
}
__device__ __forceinline__ uint32_t pack2lo(float a, float b) {
    float ra = a - __bfloat162float(__float2bfloat16(a));
    float rb = b - __bfloat162float(__float2bfloat16(b));
    return (uint32_t)__bfloat16_as_ushort(__float2bfloat16(ra))
         | ((uint32_t)__bfloat16_as_ushort(__float2bfloat16(rb)) << 16);
}
#define CP_ASYNC16(dst, src) \
    asm volatile("cp.async.cg.shared.global [%0], [%1], 16;" \
        :: "r"(dst), "l"(src) : "memory")
#define CP_COMMIT() asm volatile("cp.async.commit_group;" ::: "memory")

// ================= pack: fp32 -> hi plane + lo plane ==========================
__global__ __launch_bounds__(256) void pack_k(const float* __restrict__ X,
                                              unsigned short* __restrict__ Y,
                                              int n8, size_t plane)
{
    int g = blockIdx.x * 256 + threadIdx.x;
    if (g >= n8) return;
    float4 v0 = ((const float4*)X)[g * 2];
    float4 v1 = ((const float4*)X)[g * 2 + 1];
    uint4 hi, lo;
    hi.x = pack2hi(v0.x, v0.y); lo.x = pack2lo(v0.x, v0.y);
    hi.y = pack2hi(v0.z, v0.w); lo.y = pack2lo(v0.z, v0.w);
    hi.z = pack2hi(v1.x, v1.y); lo.z = pack2lo(v1.x, v1.y);
    hi.w = pack2hi(v1.z, v1.w); lo.w = pack2lo(v1.z, v1.w);
    *(uint4*)(Y + (size_t)g * 8)         = hi;
    *(uint4*)(Y + plane + (size_t)g * 8) = lo;
}

// ====== LayerNorm -> packed planes, with optional fused lora t = y @ A^T ======
__global__ __launch_bounds__(256) void ln_k(const float* __restrict__ X,
                                            const float* __restrict__ gw,
                                            const float* __restrict__ bw,
                                            unsigned short* __restrict__ O2,
                                            const float* __restrict__ Aw,
                                            float* __restrict__ T)
{
    const size_t PL = (size_t)MROWS * CDIM;
    const int row = blockIdx.x, t = threadIdx.x;
    const float* xr = X + (size_t)row * 1024;
    float4 v = ((const float4*)xr)[t];
    float loc[4] = {v.x, v.y, v.z, v.w};
    float sum = loc[0] + loc[1] + loc[2] + loc[3];
    __shared__ float red[256];
    __shared__ float lred[8][16];
    red[t] = sum; __syncthreads();
#pragma unroll
    for (int o = 128; o > 0; o >>= 1) { if (t < o) red[t] += red[t + o]; __syncthreads(); }
    const float mean = red[0] * (1.f / 1024.f);
    __syncthreads();
    float vs = 0.f;
#pragma unroll
    for (int i = 0; i < 4; i++) { float d = loc[i] - mean; vs += d * d; }
    red[t] = vs; __syncthreads();
#pragma unroll
    for (int o = 128; o > 0; o >>= 1) { if (t < o) red[t] += red[t + o]; __syncthreads(); }
    const float inv = rsqrtf(red[0] * (1.f / 1024.f) + 1e-5f);
    float4 gv = ((const float4*)gw)[t];
    float4 bv = ((const float4*)bw)[t];
    float y[4];
    y[0] = (loc[0] - mean) * inv * gv.x + bv.x;
    y[1] = (loc[1] - mean) * inv * gv.y + bv.y;
    y[2] = (loc[2] - mean) * inv * gv.z + bv.z;
    y[3] = (loc[3] - mean) * inv * gv.w + bv.w;
    *(uint2*)(O2 + (size_t)row * 1024 + t * 4) =
        make_uint2(pack2hi(y[0], y[1]), pack2hi(y[2], y[3]));
    *(uint2*)(O2 + PL + (size_t)row * 1024 + t * 4) =
        make_uint2(pack2lo(y[0], y[1]), pack2lo(y[2], y[3]));

    if (Aw != nullptr) {
        const int lane = t & 31, warp = t >> 5;
        float acc[16];
#pragma unroll
        for (int r = 0; r < 16; r++) {
            float4 av = *(const float4*)&Aw[r * 1024 + t * 4];
            acc[r] = y[0] * av.x + y[1] * av.y + y[2] * av.z + y[3] * av.w;
        }
#pragma unroll
        for (int r = 0; r < 16; r++) {
            float vv = acc[r];
#pragma unroll
            for (int o = 16; o > 0; o >>= 1)
                vv += __shfl_down_sync(0xffffffffu, vv, o);
            if (lane == 0) lred[warp][r] = vv;
        }
        __syncthreads();
        if (t < 16) {
            float s = 0.f;
#pragma unroll
            for (int w = 0; w < 8; w++) s += lred[w][t];
            T[(size_t)row * 16 + t] = s;
        }
    }
}

// ================= lora t = X @ A^T : fp32 input variant ======================
__global__ __launch_bounds__(256) void lora_t_k(const float* __restrict__ X,
                                                const float* __restrict__ Aw,
                                                float* __restrict__ T)
{
    const int row = blockIdx.x;
    const float* xr = X + (size_t)row * 1024;
    float acc[16];
#pragma unroll
    for (int r = 0; r < 16; r++) acc[r] = 0.f;
    for (int k = threadIdx.x; k < 1024; k += 256) {
        float xv = xr[k];
#pragma unroll
        for (int r = 0; r < 16; r++) acc[r] += xv * Aw[r * 1024 + k];
    }
    __shared__ float red[8][16];
    const int lane = threadIdx.x & 31, warp = threadIdx.x >> 5;
#pragma unroll
    for (int r = 0; r < 16; r++) {
        float v = acc[r];
#pragma unroll
        for (int o = 16; o > 0; o >>= 1) v += __shfl_down_sync(0xffffffffu, v, o);
        if (lane == 0) red[warp][r] = v;
    }
    __syncthreads();
    if (threadIdx.x < 16) {
        float s = 0.f;
#pragma unroll
        for (int w = 0; w < 8; w++) s += red[w][threadIdx.x];
        T[(size_t)row * 16 + threadIdx.x] = s;
    }
}

// ================= bf16 HMMA GEMM (R8 config: 128x128, 3-stage, 2 CTA/SM) =====
#define NSTAGE 3
#define STG_B 32768
#define GEMM_SMEM (NSTAGE * STG_B)

__global__ __launch_bounds__(256, 2) void gemm_bf16(
    const unsigned short* __restrict__ A, size_t aPl,
    const unsigned short* __restrict__ B, size_t bPl,
    const float* __restrict__ bias,
    const float* __restrict__ lT, const float* __restrict__ lB,
    const float* __restrict__ res,
    void* __restrict__ Cout, size_t cPl,
    int M, int N, int K, int flags)
{
    extern __shared__ char smem[];
    const uint32_t sb0 = smem_u32(smem);
    const int tid = threadIdx.x, lane = tid & 31, wid = tid >> 5;
    const int wm = wid >> 2, wn = wid & 3;
    const int bm = blockIdx.y * 128, bn = blockIdx.x * 128;
    const int NC = K >> 5;

    const int lr = tid & 127, side = tid >> 7;
    const unsigned short* gh = side ? B + (size_t)(bn + lr) * K
                                    : A + (size_t)(bm + lr) * K;
    const unsigned short* gl = gh + (side ? bPl : aPl);
    uint32_t dst[8];
#pragma unroll
    for (int c = 0; c < 8; c++)
        dst[c] = (uint32_t)side * 16384u + (uint32_t)lr * 128u
               + (uint32_t)((c ^ (lr & 7)) << 4);

    float acc[4][4][4];
#pragma unroll
    for (int i = 0; i < 4; i++)
#pragma unroll
        for (int j = 0; j < 4; j++)
#pragma unroll
            for (int q = 0; q < 4; q++) acc[i][j][q] = 0.f;

    auto issue = [&](int s, int kt) {
        uint32_t st = sb0 + s * STG_B;
        const unsigned short* ph = gh + kt * 32;
        const unsigned short* pl = gl + kt * 32;
#pragma unroll
        for (int c = 0; c < 4; c++)
            CP_ASYNC16(st + dst[c], ph + c * 8);
#pragma unroll
        for (int c = 4; c < 8; c++)
            CP_ASYNC16(st + dst[c], pl + (c - 4) * 8);
    };

    issue(0, 0); CP_COMMIT();
    issue(1, 1); CP_COMMIT();

    int scur = 0, snext = 2;
    for (int kt = 0; kt < NC; kt++) {
        asm volatile("cp.async.wait_group 1;" ::: "memory");
        __syncthreads();
        if (kt + 2 < NC) { issue(snext, kt + 2); CP_COMMIT();
                           snext = (snext == 2) ? 0 : snext + 1; }

        const uint32_t st = sb0 + scur * STG_B;
        scur = (scur == 2) ? 0 : scur + 1;
#pragma unroll
        for (int ks = 0; ks < 2; ks++) {
            uint32_t ah[4][4], al[4][4];
#pragma unroll
            for (int i = 0; i < 4; i++) {
                const int r = wm * 64 + i * 16 + (lane & 15);
                const int ch = ks * 2 + (lane >> 4);
                ldmatrix_x4(ah[i], st + r * 128 + ((ch ^ (r & 7)) << 4));
                ldmatrix_x4(al[i], st + r * 128 + (((ch + 4) ^ (r & 7)) << 4));
            }
#pragma unroll
            for (int jj = 0; jj < 2; jj++) {
                const int r = wn * 32 + jj * 16 + (lane & 7) + ((lane >> 4) << 3);
                const int ch = ks * 2 + ((lane >> 3) & 1);
                uint32_t bh[4], bl[4];
                ldmatrix_x4(bh, st + 16384 + r * 128 + ((ch ^ (r & 7)) << 4));
                ldmatrix_x4(bl, st + 16384 + r * 128 + (((ch + 4) ^ (r & 7)) << 4));
#pragma unroll
                for (int i = 0; i < 4; i++) {
                    mma16816(acc[i][2 * jj],     ah[i], bh[0], bh[1]);
                    mma16816(acc[i][2 * jj + 1], ah[i], bh[2], bh[3]);
                }
#pragma unroll
                for (int i = 0; i < 4; i++) {
                    mma16816(acc[i][2 * jj],     al[i], bh[0], bh[1]);
                    mma16816(acc[i][2 * jj + 1], al[i], bh[2], bh[3]);
                }
#pragma unroll
                for (int i = 0; i < 4; i++) {
                    mma16816(acc[i][2 * jj],     ah[i], bl[0], bl[1]);
                    mma16816(acc[i][2 * jj + 1], ah[i], bl[2], bl[3]);
                }
            }
        }
    }
    asm volatile("cp.async.wait_group 0;" ::: "memory");
    __syncthreads();

    float* sLT = (float*)smem;
    float* sLB = (float*)(smem + 8192);
    if (flags & F_LORA) {
        if (tid < 128) {
#pragma unroll
            for (int q = 0; q < 4; q++)
                ((float4*)&sLT[tid * 16])[q] = ((const float4*)&lT[(size_t)(bm + tid) * 16])[q];
        } else {
            int r = tid - 128;
#pragma unroll
            for (int q = 0; q < 4; q++)
                ((float4*)&sLB[r * 16])[q] = ((const float4*)&lB[(size_t)(bn + r) * 16])[q];
        }
        __syncthreads();
    }

#pragma unroll
    for (int i = 0; i < 4; i++) {
#pragma unroll
        for (int j = 0; j < 4; j++) {
            const int ml = wm * 64 + i * 16 + (lane >> 2);
            const int nl = wn * 32 + j * 8 + (lane & 3) * 2;
            float v[4] = {acc[i][j][0], acc[i][j][1], acc[i][j][2], acc[i][j][3]};
            const float b0 = bias[bn + nl], b1 = bias[bn + nl + 1];
            v[0] += b0; v[1] += b1; v[2] += b0; v[3] += b1;
            if (flags & F_LORA) {
                float s00 = 0, s01 = 0, s10 = 0, s11 = 0;
#pragma unroll
                for (int r = 0; r < 16; r++) {
                    float t0 = sLT[ml * 16 + r], t1 = sLT[(ml + 8) * 16 + r];
                    float u0 = sLB[nl * 16 + r], u1 = sLB[(nl + 1) * 16 + r];
                    s00 += t0 * u0; s01 += t0 * u1; s10 += t1 * u0; s11 += t1 * u1;
                }
                v[0] += s00 * 0.0625f; v[1] += s01 * 0.0625f;
                v[2] += s10 * 0.0625f; v[3] += s11 * 0.0625f;
            }
            if (flags & F_GELU) {
#pragma unroll
                for (int q = 0; q < 4; q++) {
                    float u = v[q];
                    float c2 = 0.7978845608028654f * (u + 0.044715f * u * u * u);
                    v[q] = 0.5f * u * (1.0f + tanhf(c2));
                }
            }
            const int m0 = bm + ml, m1 = m0 + 8, n0 = bn + nl;
            if (flags & F_RES) {
                float2 r0 = *(const float2*)&res[(size_t)m0 * N + n0];
                float2 r1 = *(const float2*)&res[(size_t)m1 * N + n0];
                v[0] += r0.x; v[1] += r0.y; v[2] += r1.x; v[3] += r1.y;
            }
            if (flags & F_PACK) {
                unsigned short* Y = (unsigned short*)Cout;
                *(uint32_t*)(Y + (size_t)m0 * N + n0)       = pack2hi(v[0], v[1]);
                *(uint32_t*)(Y + cPl + (size_t)m0 * N + n0) = pack2lo(v[0], v[1]);
                *(uint32_t*)(Y + (size_t)m1 * N + n0)       = pack2hi(v[2], v[3]);
                *(uint32_t*)(Y + cPl + (size_t)m1 * N + n0) = pack2lo(v[2], v[3]);
            } else {
                float* C = (float*)Cout;
                *(float2*)&C[(size_t)m0 * N + n0] = make_float2(v[0], v[1]);
                *(float2*)&C[(size_t)m1 * N + n0] = make_float2(v[2], v[3]);
            }
        }
    }
}

// ======= HMMA split-bf16 flash attention (packed I/O, fused lora-t out) =======
#define ATTN_SMEM 65536

__global__ __launch_bounds__(128) void attn_k(
    const unsigned short* __restrict__ Qp, int qs, size_t qPl,
    const unsigned short* __restrict__ Kp, int ks, size_t kPl,
    const unsigned short* __restrict__ Vp, int vs, size_t vPl,
    unsigned short* __restrict__ O2,
    const float* __restrict__ Aw, float* __restrict__ T)
{
    extern __shared__ char smem[];
    const uint32_t sb0 = smem_u32(smem);
    const size_t OPL = (size_t)MROWS * CDIM;
    const int qt = gridDim.x - 1 - blockIdx.x;
    const int b = blockIdx.y >> 4, h = blockIdx.y & 15;
    const int tid = threadIdx.x, lane = tid & 31, wm = tid >> 5;
    const size_t rowbase = (size_t)b * 1024;
    const int hoff = h * 64;

    const int r = tid >> 1, cg = (tid & 1) * 4;
    uint32_t dstc[4];
#pragma unroll
    for (int c = 0; c < 4; c++)
        dstc[c] = (uint32_t)r * 128u + (uint32_t)(((cg + c) ^ (r & 7)) << 4);

    {
        const unsigned short* qh = Qp + (rowbase + (size_t)qt * 64 + r) * qs + hoff;
        const unsigned short* ql = qh + qPl;
#pragma unroll
        for (int c = 0; c < 4; c++) {
            CP_ASYNC16(sb0 + dstc[c],        qh + (cg + c) * 8);
            CP_ASYNC16(sb0 + 8192 + dstc[c], ql + (cg + c) * 8);
        }
        CP_COMMIT();
        asm volatile("cp.async.wait_group 0;" ::: "memory");
    }
    __syncthreads();

    uint32_t Qh[4][4], Ql[4][4];
    {
        const int j = lane >> 3, rr2 = lane & 7;
        const int row = wm * 16 + ((j & 1) << 3) + rr2;
#pragma unroll
        for (int kc = 0; kc < 4; kc++) {
            const int col = kc * 16 + ((j >> 1) << 3);
            const uint32_t off = (uint32_t)row * 128 + ((((uint32_t)col >> 3) ^ (row & 7)) << 4);
            ldmatrix_x4(Qh[kc], sb0 + off);
            ldmatrix_x4(Ql[kc], sb0 + 8192 + off);
        }
    }
    __syncthreads();

    auto issue_kv = [&](int stage, int jt) {
        const uint32_t st = sb0 + stage * 32768;
        const size_t grow = rowbase + (size_t)jt * 64 + r;
        const unsigned short* kh = Kp + grow * ks + hoff;
        const unsigned short* vh = Vp + grow * vs + hoff;
#pragma unroll
        for (int c = 0; c < 4; c++) {
            CP_ASYNC16(st + dstc[c],         kh + (cg + c) * 8);
            CP_ASYNC16(st + 8192 + dstc[c],  kh + kPl + (cg + c) * 8);
            CP_ASYNC16(st + 16384 + dstc[c], vh + (cg + c) * 8);
            CP_ASYNC16(st + 24576 + dstc[c], vh + vPl + (cg + c) * 8);
        }
    };

    float oacc[8][4];
#pragma unroll
    for (int nt = 0; nt < 8; nt++)
#pragma unroll
        for (int q = 0; q < 4; q++) oacc[nt][q] = 0.f;
    float m0v = -1e30f, m1v = -1e30f, l0 = 0.f, l1 = 0.f;

    const int jj = lane >> 3, rr2 = lane & 7;
    const int nTiles = qt + 1;

    issue_kv(0, 0);
    CP_COMMIT();

    for (int jt = 0; jt < nTiles; jt++) {
        if (jt + 1 < nTiles) { issue_kv((jt + 1) & 1, jt + 1); CP_COMMIT(); }
        if (jt + 1 < nTiles) asm volatile("cp.async.wait_group 1;" ::: "memory");
        else                 asm volatile("cp.async.wait_group 0;" ::: "memory");
        __syncthreads();
        const uint32_t st = sb0 + (jt & 1) * 32768;

        float sacc[8][4];
#pragma unroll
        for (int nt = 0; nt < 8; nt++)
#pragma unroll
            for (int q = 0; q < 4; q++) sacc[nt][q] = 0.f;

#pragma unroll
        for (int kc = 0; kc < 4; kc++) {
#pragma unroll
            for (int p = 0; p < 4; p++) {
                const int krow = p * 16 + ((jj >> 1) << 3) + rr2;
                const int kcol = kc * 16 + ((jj & 1) << 3);
                const uint32_t off = (uint32_t)krow * 128
                                   + ((((uint32_t)kcol >> 3) ^ (krow & 7)) << 4);
                uint32_t bh[4], bl[4];
                ldmatrix_x4(bh, st + off);
                mma16816(sacc[2*p],   Qh[kc], bh[0], bh[1]);
                mma16816(sacc[2*p+1], Qh[kc], bh[2], bh[3]);
                mma16816(sacc[2*p],   Ql[kc], bh[0], bh[1]);
                mma16816(sacc[2*p+1], Ql[kc], bh[2], bh[3]);
                ldmatrix_x4(bl, st + 8192 + off);
                mma16816(sacc[2*p],   Qh[kc], bl[0], bl[1]);
                mma16816(sacc[2*p+1], Qh[kc], bl[2], bl[3]);
            }
        }
#pragma unroll
        for (int nt = 0; nt < 8; nt++)
#pragma unroll
            for (int q = 0; q < 4; q++) sacc[nt][q] *= 0.125f;

        const int rA = lane >> 2;
        if (jt == qt) {
            const int gA = wm * 16 + rA, gB = gA + 8;
#pragma unroll
            for (int nt = 0; nt < 8; nt++) {
                const int c = nt * 8 + (lane & 3) * 2;
                if (c     > gA) sacc[nt][0] = -1e30f;
                if (c + 1 > gA) sacc[nt][1] = -1e30f;
                if (c     > gB) sacc[nt][2] = -1e30f;
                if (c + 1 > gB) sacc[nt][3] = -1e30f;
            }
        }
        float mxA = -1e30f, mxB = -1e30f;
#pragma unroll
        for (int nt = 0; nt < 8; nt++) {
            mxA = fmaxf(mxA, fmaxf(sacc[nt][0], sacc[nt][1]));
            mxB = fmaxf(mxB, fmaxf(sacc[nt][2], sacc[nt][3]));
        }
        mxA = fmaxf(mxA, __shfl_xor_sync(0xffffffffu, mxA, 1));
        mxA = fmaxf(mxA, __shfl_xor_sync(0xffffffffu, mxA, 2));
        mxB = fmaxf(mxB, __shfl_xor_sync(0xffffffffu, mxB, 1));
        mxB = fmaxf(mxB, __shfl_xor_sync(0xffffffffu, mxB, 2));
        const float mnA = fmaxf(m0v, mxA), mnB = fmaxf(m1v, mxB);
        const float aA = __expf(m0v - mnA), aB = __expf(m1v - mnB);
        float sA = 0.f, sB = 0.f;
#pragma unroll
        for (int nt = 0; nt < 8; nt++) {
            float p0 = __expf(sacc[nt][0] - mnA);
            float p1 = __expf(sacc[nt][1] - mnA);
            float p2 = __expf(sacc[nt][2] - mnB);
            float p3 = __expf(sacc[nt][3] - mnB);
            sacc[nt][0] = p0; sacc[nt][1] = p1; sacc[nt][2] = p2; sacc[nt][3] = p3;
            sA += p0 + p1; sB += p2 + p3;
        }
        sA += __shfl_xor_sync(0xffffffffu, sA, 1);
        sA += __shfl_xor_sync(0xffffffffu, sA, 2);
        sB += __shfl_xor_sync(0xffffffffu, sB, 1);
        sB += __shfl_xor_sync(0xffffffffu, sB, 2);
        l0 = l0 * aA + sA; l1 = l1 * aB + sB;
        m0v = mnA; m1v = mnB;
#pragma unroll
        for (int nt = 0; nt < 8; nt++) {
            oacc[nt][0] *= aA; oacc[nt][1] *= aA;
            oacc[nt][2] *= aB; oacc[nt][3] *= aB;
        }

        uint32_t Ph[4][4], Pl[4][4];
#pragma unroll
        for (int kc = 0; kc < 4; kc++) {
            float* t0 = sacc[2 * kc];
            float* t1 = sacc[2 * kc + 1];
            Ph[kc][0] = pack2hi(t0[0], t0[1]); Pl[kc][0] = pack2lo(t0[0], t0[1]);
            Ph[kc][1] = pack2hi(t0[2], t0[3]); Pl[kc][1] = pack2lo(t0[2], t0[3]);
            Ph[kc][2] = pack2hi(t1[0], t1[1]); Pl[kc][2] = pack2lo(t1[0], t1[1]);
            Ph[kc][3] = pack2hi(t1[2], t1[3]); Pl[kc][3] = pack2lo(t1[2], t1[3]);
        }

#pragma unroll
        for (int kc = 0; kc < 4; kc++) {
            const int vrow = kc * 16 + ((jj & 1) << 3) + rr2;
#pragma unroll
            for (int p = 0; p < 4; p++) {
                const int vcol = p * 16 + ((jj >> 1) << 3);
                const uint32_t off = (uint32_t)vrow * 128
                                   + ((((uint32_t)vcol >> 3) ^ (vrow & 7)) << 4);
                uint32_t vh[4], vl[4];
                ldmatrix_x4_t(vh, st + 16384 + off);
                mma16816(oacc[2*p],   Ph[kc], vh[0], vh[1]);
                mma16816(oacc[2*p+1], Ph[kc], vh[2], vh[3]);
                mma16816(oacc[2*p],   Pl[kc], vh[0], vh[1]);
                mma16816(oacc[2*p+1], Pl[kc], vh[2], vh[3]);
                ldmatrix_x4_t(vl, st + 24576 + off);
                mma16816(oacc[2*p],   Ph[kc], vl[0], vl[1]);
                mma16816(oacc[2*p+1], Ph[kc], vl[2], vl[3]);
            }
        }
        __syncthreads();
    }

    // ---- normalize, write packed O, keep values for fused lora ----
    const float iA = 1.f / l0, iB = 1.f / l1;
    const int rA = lane >> 2;
    const int rowA = (int)(qt * 64 + wm * 16 + rA);          // within batch
    const size_t grA = (rowbase + rowA) * 1024 + hoff;
    const size_t grB = grA + 8 * 1024;
    float oA[16], oB[16];
#pragma unroll
    for (int nt = 0; nt < 8; nt++) {
        const int c = nt * 8 + (lane & 3) * 2;
        float a0 = oacc[nt][0] * iA, a1 = oacc[nt][1] * iA;
        float b0 = oacc[nt][2] * iB, b1 = oacc[nt][3] * iB;
        oA[2*nt] = a0; oA[2*nt+1] = a1; oB[2*nt] = b0; oB[2*nt+1] = b1;
        *(uint32_t*)(O2 + grA + c)       = pack2hi(a0, a1);
        *(uint32_t*)(O2 + OPL + grA + c) = pack2lo(a0, a1);
        *(uint32_t*)(O2 + grB + c)       = pack2hi(b0, b1);
        *(uint32_t*)(O2 + OPL + grB + c) = pack2lo(b0, b1);
    }

    // ---- fused lora t accumulation: T[row] += O[row, head] . A[:, head]^T ----
    if (Aw != nullptr) {
        __syncthreads();
        float* sA2 = (float*)smem;            // 16 x 64 slice of A
#pragma unroll
        for (int q = 0; q < 2; q++) {
            const int i4 = tid * 2 + q;       // 0..255 float4s
            const int rr = i4 >> 4, c4 = (i4 & 15) << 2;
            ((float4*)sA2)[i4] = *(const float4*)&Aw[rr * 1024 + hoff + c4];
        }
        __syncthreads();
        const size_t trA = rowbase + rowA;
#pragma unroll
        for (int rr = 0; rr < 16; rr++) {
            float ta = 0.f, tb = 0.f;
#pragma unroll
            for (int nt = 0; nt < 8; nt++) {
                const int c = nt * 8 + (lane & 3) * 2;
                ta += oA[2*nt] * sA2[rr * 64 + c] + oA[2*nt+1] * sA2[rr * 64 + c + 1];
                tb += oB[2*nt] * sA2[rr * 64 + c] + oB[2*nt+1] * sA2[rr * 64 + c + 1];
            }
            ta += __shfl_xor_sync(0xffffffffu, ta, 1);
            ta += __shfl_xor_sync(0xffffffffu, ta, 2);
            tb += __shfl_xor_sync(0xffffffffu, tb, 1);
            tb += __shfl_xor_sync(0xffffffffu, tb, 2);
            if ((lane & 3) == 0) {
                atomicAdd(&T[trA * 16 + rr], ta);
                atomicAdd(&T[(trA + 8) * 16 + rr], tb);
            }
        }
    }
}

// ================= host orchestration =========================================
static inline void pack_launch(const float* src, unsigned short* dst, size_t nelem) {
    int n8 = (int)(nelem / 8);
    pack_k<<<(n8 + 255) / 256, 256>>>(src, dst, n8, nelem);
}

extern "C" void kernel_launch(void* const* d_in, const int* in_sizes, int n_in,
                              void* d_out, int out_size)
{
    const float* x        = (const float*)d_in[0];
    const float* feature  = (const float*)d_in[1];
    const float* ln1_g    = (const float*)d_in[2];
    const float* ln1_b    = (const float*)d_in[3];
    const float* ln2_g    = (const float*)d_in[4];
    const float* ln2_b    = (const float*)d_in[5];
    const float* sa_qkv_w = (const float*)d_in[6];
    const float* sa_qkv_b = (const float*)d_in[7];
    const float* sa_qkv_a = (const float*)d_in[8];
    const float* sa_qkv_lb= (const float*)d_in[9];
    const float* sa_pr_w  = (const float*)d_in[10];
    const float* sa_pr_b  = (const float*)d_in[11];
    const float* sa_pr_a  = (const float*)d_in[12];
    const float* sa_pr_lb = (const float*)d_in[13];
    const float* ca_q_w   = (const float*)d_in[14];
    const float* ca_q_b   = (const float*)d_in[15];
    const float* ca_q_a   = (const float*)d_in[16];
    const float* ca_q_lb  = (const float*)d_in[17];
    const float* ca_kv_w  = (const float*)d_in[18];
    const float* ca_kv_b  = (const float*)d_in[19];
    const float* ca_kv_a  = (const float*)d_in[20];
    const float* ca_kv_lb = (const float*)d_in[21];
    const float* ca_pr_w  = (const float*)d_in[22];
    const float* ca_pr_b  = (const float*)d_in[23];
    const float* ca_pr_a  = (const float*)d_in[24];
    const float* ca_pr_lb = (const float*)d_in[25];
    const float* fc_w     = (const float*)d_in[26];
    const float* fc_b     = (const float*)d_in[27];
    const float* pr_w     = (const float*)d_in[28];
    const float* pr_b     = (const float*)d_in[29];

    float* xo = (float*)d_out;

    float* t;
    unsigned short *h2, *o2, *f2, *qkv2, *kv2, *mlp2;
    unsigned short *wqkv2, *wsap2, *wcaq2, *wcakv2, *wcap2, *wfc2, *wpr2;
    cudaGetSymbolAddress((void**)&t,     g_t);
    cudaGetSymbolAddress((void**)&h2,    g_h2);
    cudaGetSymbolAddress((void**)&o2,    g_o2);
    cudaGetSymbolAddress((void**)&f2,    g_f2);
    cudaGetSymbolAddress((void**)&qkv2,  g_qkv2);
    cudaGetSymbolAddress((void**)&kv2,   g_kv2);
    cudaGetSymbolAddress((void**)&mlp2,  g_mlp2);
    cudaGetSymbolAddress((void**)&wqkv2, g_wqkv2);
    cudaGetSymbolAddress((void**)&wsap2, g_wsap2);
    cudaGetSymbolAddress((void**)&wcaq2, g_wcaq2);
    cudaGetSymbolAddress((void**)&wcakv2,g_wcakv2);
    cudaGetSymbolAddress((void**)&wcap2, g_wcap2);
    cudaGetSymbolAddress((void**)&wfc2,  g_wfc2);
    cudaGetSymbolAddress((void**)&wpr2,  g_wpr2);

    cudaFuncSetAttribute(gemm_bf16, cudaFuncAttributeMaxDynamicSharedMemorySize,
                         GEMM_SMEM);
    cudaFuncSetAttribute(attn_k, cudaFuncAttributeMaxDynamicSharedMemorySize,
                         ATTN_SMEM);

    cudaMemcpyAsync(xo, x, (size_t)MROWS * CDIM * sizeof(float),
                    cudaMemcpyDeviceToDevice);

    const size_t PC = (size_t)CDIM * CDIM;
    const size_t PA = (size_t)MROWS * CDIM;
    const size_t TB = (size_t)MROWS * 16 * sizeof(float);

    // ---- self attention ----
    pack_launch(sa_qkv_w, wqkv2, 3 * PC);
    ln_k    <<<MROWS, 256>>>(xo, ln1_g, ln1_b, h2, sa_qkv_a, t);
    gemm_bf16<<<dim3(24, 32), 256, GEMM_SMEM>>>(
        h2, PA, wqkv2, 3 * PC, sa_qkv_b, t, sa_qkv_lb,
        nullptr, qkv2, 3 * PA, MROWS, 3072, 1024, F_LORA | F_PACK);
    pack_launch(feature, f2, PA);
    cudaMemsetAsync(t, 0, TB);
    attn_k  <<<dim3(16, 64), 128, ATTN_SMEM>>>(
        qkv2, 3072, 3 * PA, qkv2 + 1024, 3072, 3 * PA, qkv2 + 2048, 3072, 3 * PA,
        o2, sa_pr_a, t);
    pack_launch(sa_pr_w, wsap2, PC);
    gemm_bf16<<<dim3(8, 32), 256, GEMM_SMEM>>>(
        o2, PA, wsap2, PC, sa_pr_b, t, sa_pr_lb,
        xo, xo, 0, MROWS, 1024, 1024, F_LORA | F_RES);

    // ---- cross attention (tri(T,S) == causal since T==S) ----
    ln_k    <<<MROWS, 256>>>(xo, ln1_g, ln1_b, h2, ca_q_a, t);
    pack_launch(ca_q_w, wcaq2, PC);
    gemm_bf16<<<dim3(8, 32), 256, GEMM_SMEM>>>(
        h2, PA, wcaq2, PC, ca_q_b, t, ca_q_lb,
        nullptr, qkv2, PA, MROWS, 1024, 1024, F_LORA | F_PACK);
    pack_launch(ca_kv_w, wcakv2, 2 * PC);
    lora_t_k<<<MROWS, 256>>>(feature, ca_kv_a, t);
    gemm_bf16<<<dim3(16, 32), 256, GEMM_SMEM>>>(
        f2, PA, wcakv2, 2 * PC, ca_kv_b, t, ca_kv_lb,
        nullptr, kv2, 2 * PA, MROWS, 2048, 1024, F_LORA | F_PACK);
    cudaMemsetAsync(t, 0, TB);
    attn_k  <<<dim3(16, 64), 128, ATTN_SMEM>>>(
        qkv2, 1024, PA, kv2, 2048, 2 * PA, kv2 + 1024, 2048, 2 * PA,
        o2, ca_pr_a, t);
    pack_launch(ca_pr_w, wcap2, PC);
    gemm_bf16<<<dim3(8, 32), 256, GEMM_SMEM>>>(
        o2, PA, wcap2, PC, ca_pr_b, t, ca_pr_lb,
        xo, xo, 0, MROWS, 1024, 1024, F_LORA | F_RES);

    // ---- MLP ----
    ln_k    <<<MROWS, 256>>>(xo, ln2_g, ln2_b, h2, nullptr, nullptr);
    pack_launch(fc_w, wfc2, 4 * PC);
    gemm_bf16<<<dim3(32, 32), 256, GEMM_SMEM>>>(
        h2, PA, wfc2, 4 * PC, fc_b, nullptr, nullptr,
        nullptr, mlp2, 4 * PA, MROWS, 4096, 1024, F_GELU | F_PACK);
    pack_launch(pr_w, wpr2, 4 * PC);
    gemm_bf16<<<dim3(8, 32), 256, GEMM_SMEM>>>(
        mlp2, 4 * PA, wpr2, 4 * PC, pr_b, nullptr, nullptr,
        xo, xo, 0, MROWS, 1024, 4096, F_RES);
}

// round 14
// speedup vs baseline: 1.5311x; 1.5311x over previous
#include <cuda_runtime.h>
#include <cuda_bf16.h>
#include <cstdint>

// ================= scratch (device globals; allocation-free) ==================
#define MROWS 4096
#define CDIM  1024

__device__ float g_t  [MROWS * 16];
__device__ unsigned short g_h2  [(size_t)2 * MROWS * CDIM];
__device__ unsigned short g_o2  [(size_t)2 * MROWS * CDIM];
__device__ unsigned short g_f2  [(size_t)2 * MROWS * CDIM];
__device__ unsigned short g_qkv2[(size_t)2 * MROWS * 3 * CDIM];
__device__ unsigned short g_kv2 [(size_t)2 * MROWS * 2 * CDIM];
__device__ unsigned short g_mlp2[(size_t)2 * MROWS * 4 * CDIM];
__device__ unsigned short g_wqkv2 [(size_t)2 * 3 * CDIM * CDIM];
__device__ unsigned short g_wsap2 [(size_t)2 * CDIM * CDIM];
__device__ unsigned short g_wcaq2 [(size_t)2 * CDIM * CDIM];
__device__ unsigned short g_wcakv2[(size_t)2 * 2 * CDIM * CDIM];
__device__ unsigned short g_wcap2 [(size_t)2 * CDIM * CDIM];
__device__ unsigned short g_wfc2  [(size_t)2 * 4 * CDIM * CDIM];
__device__ unsigned short g_wpr2  [(size_t)2 * CDIM * 4 * CDIM];

static const int F_LORA = 1, F_GELU = 2, F_RES = 4, F_PACK = 8;

// ================= helpers ====================================================
__device__ __forceinline__ uint32_t smem_u32(const void* p) {
    uint32_t a;
    asm("{ .reg .u64 t; cvta.to.shared.u64 t, %1; cvt.u32.u64 %0, t; }"
        : "=r"(a) : "l"(p));
    return a;
}
__device__ __forceinline__ void ldmatrix_x4(uint32_t* r, uint32_t addr) {
    asm volatile("ldmatrix.sync.aligned.m8n8.x4.shared.b16 {%0,%1,%2,%3}, [%4];"
        : "=r"(r[0]), "=r"(r[1]), "=r"(r[2]), "=r"(r[3]) : "r"(addr));
}
__device__ __forceinline__ void ldmatrix_x4_t(uint32_t* r, uint32_t addr) {
    asm volatile("ldmatrix.sync.aligned.m8n8.x4.trans.shared.b16 {%0,%1,%2,%3}, [%4];"
        : "=r"(r[0]), "=r"(r[1]), "=r"(r[2]), "=r"(r[3]) : "r"(addr));
}
__device__ __forceinline__ void mma16816(float* c, const uint32_t* a,
                                         uint32_t b0, uint32_t b1) {
    asm volatile("mma.sync.aligned.m16n8k16.row.col.f32.bf16.bf16.f32 "
        "{%0,%1,%2,%3}, {%4,%5,%6,%7}, {%8,%9}, {%0,%1,%2,%3};"
        : "+f"(c[0]), "+f"(c[1]), "+f"(c[2]), "+f"(c[3])
        : "r"(a[0]), "r"(a[1]), "r"(a[2]), "r"(a[3]), "r"(b0), "r"(b1));
}
__device__ __forceinline__ uint32_t pack2hi(float a, float b) {
    return (uint32_t)__bfloat16_as_ushort(__float2bfloat16(a))
         | ((uint32_t)__bfloat16_as_ushort(__float2bfloat16(b)) << 16);
}
__device__ __forceinline__ uint32_t pack2lo(float a, float b) {
    float ra = a - __bfloat162float(__float2bfloat16(a));
    float rb = b - __bfloat162float(__float2bfloat16(b));
    return (uint32_t)__bfloat16_as_ushort(__float2bfloat16(ra))
         | ((uint32_t)__bfloat16_as_ushort(__float2bfloat16(rb)) << 16);
}
#define CP_ASYNC16(dst, src) \
    asm volatile("cp.async.cg.shared.global [%0], [%1], 16;" \
        :: "r"(dst), "l"(src) : "memory")
#define CP_COMMIT() asm volatile("cp.async.commit_group;" ::: "memory")

// ================= pack: fp32 -> hi plane + lo plane ==========================
__global__ __launch_bounds__(256) void pack_k(const float* __restrict__ X,
                                              unsigned short* __restrict__ Y,
                                              int n8, size_t plane)
{
    int g = blockIdx.x * 256 + threadIdx.x;
    if (g >= n8) return;
    float4 v0 = ((const float4*)X)[g * 2];
    float4 v1 = ((const float4*)X)[g * 2 + 1];
    uint4 hi, lo;
    hi.x = pack2hi(v0.x, v0.y); lo.x = pack2lo(v0.x, v0.y);
    hi.y = pack2hi(v0.z, v0.w); lo.y = pack2lo(v0.z, v0.w);
    hi.z = pack2hi(v1.x, v1.y); lo.z = pack2lo(v1.x, v1.y);
    hi.w = pack2hi(v1.z, v1.w); lo.w = pack2lo(v1.z, v1.w);
    *(uint4*)(Y + (size_t)g * 8)         = hi;
    *(uint4*)(Y + plane + (size_t)g * 8) = lo;
}

// ======= pack rows + fused lora t = x @ A^T (one block per row) ===============
__global__ __launch_bounds__(256) void pack_lora_k(const float* __restrict__ X,
                                                   unsigned short* __restrict__ Y,
                                                   size_t plane,
                                                   const float* __restrict__ Aw,
                                                   float* __restrict__ T)
{
    const int row = blockIdx.x, t = threadIdx.x;
    const float* xr = X + (size_t)row * 1024;
    float4 v = ((const float4*)xr)[t];
    *(uint2*)(Y + (size_t)row * 1024 + t * 4) =
        make_uint2(pack2hi(v.x, v.y), pack2hi(v.z, v.w));
    *(uint2*)(Y + plane + (size_t)row * 1024 + t * 4) =
        make_uint2(pack2lo(v.x, v.y), pack2lo(v.z, v.w));

    __shared__ float lred[8][16];
    const int lane = t & 31, warp = t >> 5;
    float acc[16];
#pragma unroll
    for (int r = 0; r < 16; r++) {
        float4 av = *(const float4*)&Aw[r * 1024 + t * 4];
        acc[r] = v.x * av.x + v.y * av.y + v.z * av.z + v.w * av.w;
    }
#pragma unroll
    for (int r = 0; r < 16; r++) {
        float vv = acc[r];
#pragma unroll
        for (int o = 16; o > 0; o >>= 1)
            vv += __shfl_down_sync(0xffffffffu, vv, o);
        if (lane == 0) lred[warp][r] = vv;
    }
    __syncthreads();
    if (t < 16) {
        float s = 0.f;
#pragma unroll
        for (int w = 0; w < 8; w++) s += lred[w][t];
        T[(size_t)row * 16 + t] = s;
    }
}

// ====== LayerNorm -> packed planes, with optional fused lora t = y @ A^T ======
__global__ __launch_bounds__(256) void ln_k(const float* __restrict__ X,
                                            const float* __restrict__ gw,
                                            const float* __restrict__ bw,
                                            unsigned short* __restrict__ O2,
                                            const float* __restrict__ Aw,
                                            float* __restrict__ T)
{
    const size_t PL = (size_t)MROWS * CDIM;
    const int row = blockIdx.x, t = threadIdx.x;
    const float* xr = X + (size_t)row * 1024;
    float4 v = ((const float4*)xr)[t];
    float loc[4] = {v.x, v.y, v.z, v.w};
    float sum = loc[0] + loc[1] + loc[2] + loc[3];
    __shared__ float red[256];
    __shared__ float lred[8][16];
    red[t] = sum; __syncthreads();
#pragma unroll
    for (int o = 128; o > 0; o >>= 1) { if (t < o) red[t] += red[t + o]; __syncthreads(); }
    const float mean = red[0] * (1.f / 1024.f);
    __syncthreads();
    float vs = 0.f;
#pragma unroll
    for (int i = 0; i < 4; i++) { float d = loc[i] - mean; vs += d * d; }
    red[t] = vs; __syncthreads();
#pragma unroll
    for (int o = 128; o > 0; o >>= 1) { if (t < o) red[t] += red[t + o]; __syncthreads(); }
    const float inv = rsqrtf(red[0] * (1.f / 1024.f) + 1e-5f);
    float4 gv = ((const float4*)gw)[t];
    float4 bv = ((const float4*)bw)[t];
    float y[4];
    y[0] = (loc[0] - mean) * inv * gv.x + bv.x;
    y[1] = (loc[1] - mean) * inv * gv.y + bv.y;
    y[2] = (loc[2] - mean) * inv * gv.z + bv.z;
    y[3] = (loc[3] - mean) * inv * gv.w + bv.w;
    *(uint2*)(O2 + (size_t)row * 1024 + t * 4) =
        make_uint2(pack2hi(y[0], y[1]), pack2hi(y[2], y[3]));
    *(uint2*)(O2 + PL + (size_t)row * 1024 + t * 4) =
        make_uint2(pack2lo(y[0], y[1]), pack2lo(y[2], y[3]));

    if (Aw != nullptr) {
        const int lane = t & 31, warp = t >> 5;
        float acc[16];
#pragma unroll
        for (int r = 0; r < 16; r++) {
            float4 av = *(const float4*)&Aw[r * 1024 + t * 4];
            acc[r] = y[0] * av.x + y[1] * av.y + y[2] * av.z + y[3] * av.w;
        }
#pragma unroll
        for (int r = 0; r < 16; r++) {
            float vv = acc[r];
#pragma unroll
            for (int o = 16; o > 0; o >>= 1)
                vv += __shfl_down_sync(0xffffffffu, vv, o);
            if (lane == 0) lred[warp][r] = vv;
        }
        __syncthreads();
        if (t < 16) {
            float s = 0.f;
#pragma unroll
            for (int w = 0; w < 8; w++) s += lred[w][t];
            T[(size_t)row * 16 + t] = s;
        }
    }
}

// ================= lora t: packed hi/lo input variant =========================
__global__ __launch_bounds__(256) void lora_tp_k(const unsigned short* __restrict__ X2,
                                                 const float* __restrict__ Aw,
                                                 float* __restrict__ T)
{
    const size_t PL = (size_t)MROWS * CDIM;
    const int row = blockIdx.x;
    const unsigned short* xh = X2 + (size_t)row * 1024;
    const unsigned short* xl = xh + PL;
    float acc[16];
#pragma unroll
    for (int r = 0; r < 16; r++) acc[r] = 0.f;
    for (int k = threadIdx.x; k < 1024; k += 256) {
        float xv = __bfloat162float(__ushort_as_bfloat16(xh[k]))
                 + __bfloat162float(__ushort_as_bfloat16(xl[k]));
#pragma unroll
        for (int r = 0; r < 16; r++) acc[r] += xv * Aw[r * 1024 + k];
    }
    __shared__ float red[8][16];
    const int lane = threadIdx.x & 31, warp = threadIdx.x >> 5;
#pragma unroll
    for (int r = 0; r < 16; r++) {
        float v = acc[r];
#pragma unroll
        for (int o = 16; o > 0; o >>= 1) v += __shfl_down_sync(0xffffffffu, v, o);
        if (lane == 0) red[warp][r] = v;
    }
    __syncthreads();
    if (threadIdx.x < 16) {
        float s = 0.f;
#pragma unroll
        for (int w = 0; w < 8; w++) s += red[w][threadIdx.x];
        T[(size_t)row * 16 + threadIdx.x] = s;
    }
}

// ================= bf16 HMMA GEMM (R8 config: 128x128, 3-stage, 2 CTA/SM) =====
#define NSTAGE 3
#define STG_B 32768
#define GEMM_SMEM (NSTAGE * STG_B)

__global__ __launch_bounds__(256, 2) void gemm_bf16(
    const unsigned short* __restrict__ A, size_t aPl,
    const unsigned short* __restrict__ B, size_t bPl,
    const float* __restrict__ bias,
    const float* __restrict__ lT, const float* __restrict__ lB,
    const float* __restrict__ res,
    void* __restrict__ Cout, size_t cPl,
    int M, int N, int K, int flags)
{
    extern __shared__ char smem[];
    const uint32_t sb0 = smem_u32(smem);
    const int tid = threadIdx.x, lane = tid & 31, wid = tid >> 5;
    const int wm = wid >> 2, wn = wid & 3;
    const int bm = blockIdx.y * 128, bn = blockIdx.x * 128;
    const int NC = K >> 5;

    const int lr = tid & 127, side = tid >> 7;
    const unsigned short* gh = side ? B + (size_t)(bn + lr) * K
                                    : A + (size_t)(bm + lr) * K;
    const unsigned short* gl = gh + (side ? bPl : aPl);
    uint32_t dst[8];
#pragma unroll
    for (int c = 0; c < 8; c++)
        dst[c] = (uint32_t)side * 16384u + (uint32_t)lr * 128u
               + (uint32_t)((c ^ (lr & 7)) << 4);

    float acc[4][4][4];
#pragma unroll
    for (int i = 0; i < 4; i++)
#pragma unroll
        for (int j = 0; j < 4; j++)
#pragma unroll
            for (int q = 0; q < 4; q++) acc[i][j][q] = 0.f;

    auto issue = [&](int s, int kt) {
        uint32_t st = sb0 + s * STG_B;
        const unsigned short* ph = gh + kt * 32;
        const unsigned short* pl = gl + kt * 32;
#pragma unroll
        for (int c = 0; c < 4; c++)
            CP_ASYNC16(st + dst[c], ph + c * 8);
#pragma unroll
        for (int c = 4; c < 8; c++)
            CP_ASYNC16(st + dst[c], pl + (c - 4) * 8);
    };

    issue(0, 0); CP_COMMIT();
    issue(1, 1); CP_COMMIT();

    int scur = 0, snext = 2;
    for (int kt = 0; kt < NC; kt++) {
        asm volatile("cp.async.wait_group 1;" ::: "memory");
        __syncthreads();
        if (kt + 2 < NC) { issue(snext, kt + 2); CP_COMMIT();
                           snext = (snext == 2) ? 0 : snext + 1; }

        const uint32_t st = sb0 + scur * STG_B;
        scur = (scur == 2) ? 0 : scur + 1;
#pragma unroll
        for (int ks = 0; ks < 2; ks++) {
            uint32_t ah[4][4], al[4][4];
#pragma unroll
            for (int i = 0; i < 4; i++) {
                const int r = wm * 64 + i * 16 + (lane & 15);
                const int ch = ks * 2 + (lane >> 4);
                ldmatrix_x4(ah[i], st + r * 128 + ((ch ^ (r & 7)) << 4));
                ldmatrix_x4(al[i], st + r * 128 + (((ch + 4) ^ (r & 7)) << 4));
            }
#pragma unroll
            for (int jj = 0; jj < 2; jj++) {
                const int r = wn * 32 + jj * 16 + (lane & 7) + ((lane >> 4) << 3);
                const int ch = ks * 2 + ((lane >> 3) & 1);
                uint32_t bh[4], bl[4];
                ldmatrix_x4(bh, st + 16384 + r * 128 + ((ch ^ (r & 7)) << 4));
                ldmatrix_x4(bl, st + 16384 + r * 128 + (((ch + 4) ^ (r & 7)) << 4));
#pragma unroll
                for (int i = 0; i < 4; i++) {
                    mma16816(acc[i][2 * jj],     ah[i], bh[0], bh[1]);
                    mma16816(acc[i][2 * jj + 1], ah[i], bh[2], bh[3]);
                }
#pragma unroll
                for (int i = 0; i < 4; i++) {
                    mma16816(acc[i][2 * jj],     al[i], bh[0], bh[1]);
                    mma16816(acc[i][2 * jj + 1], al[i], bh[2], bh[3]);
                }
#pragma unroll
                for (int i = 0; i < 4; i++) {
                    mma16816(acc[i][2 * jj],     ah[i], bl[0], bl[1]);
                    mma16816(acc[i][2 * jj + 1], ah[i], bl[2], bl[3]);
                }
            }
        }
    }
    asm volatile("cp.async.wait_group 0;" ::: "memory");
    __syncthreads();

    float* sLT = (float*)smem;
    float* sLB = (float*)(smem + 8192);
    if (flags & F_LORA) {
        if (tid < 128) {
#pragma unroll
            for (int q = 0; q < 4; q++)
                ((float4*)&sLT[tid * 16])[q] = ((const float4*)&lT[(size_t)(bm + tid) * 16])[q];
        } else {
            int r = tid - 128;
#pragma unroll
            for (int q = 0; q < 4; q++)
                ((float4*)&sLB[r * 16])[q] = ((const float4*)&lB[(size_t)(bn + r) * 16])[q];
        }
        __syncthreads();
    }

#pragma unroll
    for (int i = 0; i < 4; i++) {
#pragma unroll
        for (int j = 0; j < 4; j++) {
            const int ml = wm * 64 + i * 16 + (lane >> 2);
            const int nl = wn * 32 + j * 8 + (lane & 3) * 2;
            float v[4] = {acc[i][j][0], acc[i][j][1], acc[i][j][2], acc[i][j][3]};
            const float b0 = bias[bn + nl], b1 = bias[bn + nl + 1];
            v[0] += b0; v[1] += b1; v[2] += b0; v[3] += b1;
            if (flags & F_LORA) {
                float s00 = 0, s01 = 0, s10 = 0, s11 = 0;
#pragma unroll
                for (int r = 0; r < 16; r++) {
                    float t0 = sLT[ml * 16 + r], t1 = sLT[(ml + 8) * 16 + r];
                    float u0 = sLB[nl * 16 + r], u1 = sLB[(nl + 1) * 16 + r];
                    s00 += t0 * u0; s01 += t0 * u1; s10 += t1 * u0; s11 += t1 * u1;
                }
                v[0] += s00 * 0.0625f; v[1] += s01 * 0.0625f;
                v[2] += s10 * 0.0625f; v[3] += s11 * 0.0625f;
            }
            if (flags & F_GELU) {
#pragma unroll
                for (int q = 0; q < 4; q++) {
                    float u = v[q];
                    float c2 = 0.7978845608028654f * (u + 0.044715f * u * u * u);
                    v[q] = 0.5f * u * (1.0f + tanhf(c2));
                }
            }
            const int m0 = bm + ml, m1 = m0 + 8, n0 = bn + nl;
            if (flags & F_RES) {
                float2 r0 = *(const float2*)&res[(size_t)m0 * N + n0];
                float2 r1 = *(const float2*)&res[(size_t)m1 * N + n0];
                v[0] += r0.x; v[1] += r0.y; v[2] += r1.x; v[3] += r1.y;
            }
            if (flags & F_PACK) {
                unsigned short* Y = (unsigned short*)Cout;
                *(uint32_t*)(Y + (size_t)m0 * N + n0)       = pack2hi(v[0], v[1]);
                *(uint32_t*)(Y + cPl + (size_t)m0 * N + n0) = pack2lo(v[0], v[1]);
                *(uint32_t*)(Y + (size_t)m1 * N + n0)       = pack2hi(v[2], v[3]);
                *(uint32_t*)(Y + cPl + (size_t)m1 * N + n0) = pack2lo(v[2], v[3]);
            } else {
                float* C = (float*)Cout;
                *(float2*)&C[(size_t)m0 * N + n0] = make_float2(v[0], v[1]);
                *(float2*)&C[(size_t)m1 * N + n0] = make_float2(v[2], v[3]);
            }
        }
    }
}

// ================= HMMA split-bf16 flash attention (packed I/O) ===============
#define ATTN_SMEM 65536

__global__ __launch_bounds__(128) void attn_k(
    const unsigned short* __restrict__ Qp, int qs, size_t qPl,
    const unsigned short* __restrict__ Kp, int ks, size_t kPl,
    const unsigned short* __restrict__ Vp, int vs, size_t vPl,
    unsigned short* __restrict__ O2)
{
    extern __shared__ char smem[];
    const uint32_t sb0 = smem_u32(smem);
    const size_t OPL = (size_t)MROWS * CDIM;
    const int qt = gridDim.x - 1 - blockIdx.x;
    const int b = blockIdx.y >> 4, h = blockIdx.y & 15;
    const int tid = threadIdx.x, lane = tid & 31, wm = tid >> 5;
    const size_t rowbase = (size_t)b * 1024;
    const int hoff = h * 64;

    const int r = tid >> 1, cg = (tid & 1) * 4;
    uint32_t dstc[4];
#pragma unroll
    for (int c = 0; c < 4; c++)
        dstc[c] = (uint32_t)r * 128u + (uint32_t)(((cg + c) ^ (r & 7)) << 4);

    {
        const unsigned short* qh = Qp + (rowbase + (size_t)qt * 64 + r) * qs + hoff;
        const unsigned short* ql = qh + qPl;
#pragma unroll
        for (int c = 0; c < 4; c++) {
            CP_ASYNC16(sb0 + dstc[c],        qh + (cg + c) * 8);
            CP_ASYNC16(sb0 + 8192 + dstc[c], ql + (cg + c) * 8);
        }
        CP_COMMIT();
        asm volatile("cp.async.wait_group 0;" ::: "memory");
    }
    __syncthreads();

    uint32_t Qh[4][4], Ql[4][4];
    {
        const int j = lane >> 3, rr2 = lane & 7;
        const int row = wm * 16 + ((j & 1) << 3) + rr2;
#pragma unroll
        for (int kc = 0; kc < 4; kc++) {
            const int col = kc * 16 + ((j >> 1) << 3);
            const uint32_t off = (uint32_t)row * 128 + ((((uint32_t)col >> 3) ^ (row & 7)) << 4);
            ldmatrix_x4(Qh[kc], sb0 + off);
            ldmatrix_x4(Ql[kc], sb0 + 8192 + off);
        }
    }
    __syncthreads();

    auto issue_kv = [&](int stage, int jt) {
        const uint32_t st = sb0 + stage * 32768;
        const size_t grow = rowbase + (size_t)jt * 64 + r;
        const unsigned short* kh = Kp + grow * ks + hoff;
        const unsigned short* vh = Vp + grow * vs + hoff;
#pragma unroll
        for (int c = 0; c < 4; c++) {
            CP_ASYNC16(st + dstc[c],         kh + (cg + c) * 8);
            CP_ASYNC16(st + 8192 + dstc[c],  kh + kPl + (cg + c) * 8);
            CP_ASYNC16(st + 16384 + dstc[c], vh + (cg + c) * 8);
            CP_ASYNC16(st + 24576 + dstc[c], vh + vPl + (cg + c) * 8);
        }
    };

    float oacc[8][4];
#pragma unroll
    for (int nt = 0; nt < 8; nt++)
#pragma unroll
        for (int q = 0; q < 4; q++) oacc[nt][q] = 0.f;
    float m0v = -1e30f, m1v = -1e30f, l0 = 0.f, l1 = 0.f;

    const int jj = lane >> 3, rr2 = lane & 7;
    const int nTiles = qt + 1;

    issue_kv(0, 0);
    CP_COMMIT();

    for (int jt = 0; jt < nTiles; jt++) {
        if (jt + 1 < nTiles) { issue_kv((jt + 1) & 1, jt + 1); CP_COMMIT(); }
        if (jt + 1 < nTiles) asm volatile("cp.async.wait_group 1;" ::: "memory");
        else                 asm volatile("cp.async.wait_group 0;" ::: "memory");
        __syncthreads();
        const uint32_t st = sb0 + (jt & 1) * 32768;

        float sacc[8][4];
#pragma unroll
        for (int nt = 0; nt < 8; nt++)
#pragma unroll
            for (int q = 0; q < 4; q++) sacc[nt][q] = 0.f;

#pragma unroll
        for (int kc = 0; kc < 4; kc++) {
#pragma unroll
            for (int p = 0; p < 4; p++) {
                const int krow = p * 16 + ((jj >> 1) << 3) + rr2;
                const int kcol = kc * 16 + ((jj & 1) << 3);
                const uint32_t off = (uint32_t)krow * 128
                                   + ((((uint32_t)kcol >> 3) ^ (krow & 7)) << 4);
                uint32_t bh[4], bl[4];
                ldmatrix_x4(bh, st + off);
                mma16816(sacc[2*p],   Qh[kc], bh[0], bh[1]);
                mma16816(sacc[2*p+1], Qh[kc], bh[2], bh[3]);
                mma16816(sacc[2*p],   Ql[kc], bh[0], bh[1]);
                mma16816(sacc[2*p+1], Ql[kc], bh[2], bh[3]);
                ldmatrix_x4(bl, st + 8192 + off);
                mma16816(sacc[2*p],   Qh[kc], bl[0], bl[1]);
                mma16816(sacc[2*p+1], Qh[kc], bl[2], bl[3]);
            }
        }
#pragma unroll
        for (int nt = 0; nt < 8; nt++)
#pragma unroll
            for (int q = 0; q < 4; q++) sacc[nt][q] *= 0.125f;

        const int rA = lane >> 2;
        if (jt == qt) {
            const int gA = wm * 16 + rA, gB = gA + 8;
#pragma unroll
            for (int nt = 0; nt < 8; nt++) {
                const int c = nt * 8 + (lane & 3) * 2;
                if (c     > gA) sacc[nt][0] = -1e30f;
                if (c + 1 > gA) sacc[nt][1] = -1e30f;
                if (c     > gB) sacc[nt][2] = -1e30f;
                if (c + 1 > gB) sacc[nt][3] = -1e30f;
            }
        }
        float mxA = -1e30f, mxB = -1e30f;
#pragma unroll
        for (int nt = 0; nt < 8; nt++) {
            mxA = fmaxf(mxA, fmaxf(sacc[nt][0], sacc[nt][1]));
            mxB = fmaxf(mxB, fmaxf(sacc[nt][2], sacc[nt][3]));
        }
        mxA = fmaxf(mxA, __shfl_xor_sync(0xffffffffu, mxA, 1));
        mxA = fmaxf(mxA, __shfl_xor_sync(0xffffffffu, mxA, 2));
        mxB = fmaxf(mxB, __shfl_xor_sync(0xffffffffu, mxB, 1));
        mxB = fmaxf(mxB, __shfl_xor_sync(0xffffffffu, mxB, 2));
        const float mnA = fmaxf(m0v, mxA), mnB = fmaxf(m1v, mxB);
        const float aA = __expf(m0v - mnA), aB = __expf(m1v - mnB);
        float sA = 0.f, sB = 0.f;
#pragma unroll
        for (int nt = 0; nt < 8; nt++) {
            float p0 = __expf(sacc[nt][0] - mnA);
            float p1 = __expf(sacc[nt][1] - mnA);
            float p2 = __expf(sacc[nt][2] - mnB);
            float p3 = __expf(sacc[nt][3] - mnB);
            sacc[nt][0] = p0; sacc[nt][1] = p1; sacc[nt][2] = p2; sacc[nt][3] = p3;
            sA += p0 + p1; sB += p2 + p3;
        }
        sA += __shfl_xor_sync(0xffffffffu, sA, 1);
        sA += __shfl_xor_sync(0xffffffffu, sA, 2);
        sB += __shfl_xor_sync(0xffffffffu, sB, 1);
        sB += __shfl_xor_sync(0xffffffffu, sB, 2);
        l0 = l0 * aA + sA; l1 = l1 * aB + sB;
        m0v = mnA; m1v = mnB;
#pragma unroll
        for (int nt = 0; nt < 8; nt++) {
            oacc[nt][0] *= aA; oacc[nt][1] *= aA;
            oacc[nt][2] *= aB; oacc[nt][3] *= aB;
        }

        uint32_t Ph[4][4], Pl[4][4];
#pragma unroll
        for (int kc = 0; kc < 4; kc++) {
            float* t0 = sacc[2 * kc];
            float* t1 = sacc[2 * kc + 1];
            Ph[kc][0] = pack2hi(t0[0], t0[1]); Pl[kc][0] = pack2lo(t0[0], t0[1]);
            Ph[kc][1] = pack2hi(t0[2], t0[3]); Pl[kc][1] = pack2lo(t0[2], t0[3]);
            Ph[kc][2] = pack2hi(t1[0], t1[1]); Pl[kc][2] = pack2lo(t1[0], t1[1]);
            Ph[kc][3] = pack2hi(t1[2], t1[3]); Pl[kc][3] = pack2lo(t1[2], t1[3]);
        }

#pragma unroll
        for (int kc = 0; kc < 4; kc++) {
            const int vrow = kc * 16 + ((jj & 1) << 3) + rr2;
#pragma unroll
            for (int p = 0; p < 4; p++) {
                const int vcol = p * 16 + ((jj >> 1) << 3);
                const uint32_t off = (uint32_t)vrow * 128
                                   + ((((uint32_t)vcol >> 3) ^ (vrow & 7)) << 4);
                uint32_t vh[4], vl[4];
                ldmatrix_x4_t(vh, st + 16384 + off);
                mma16816(oacc[2*p],   Ph[kc], vh[0], vh[1]);
                mma16816(oacc[2*p+1], Ph[kc], vh[2], vh[3]);
                mma16816(oacc[2*p],   Pl[kc], vh[0], vh[1]);
                mma16816(oacc[2*p+1], Pl[kc], vh[2], vh[3]);
                ldmatrix_x4_t(vl, st + 24576 + off);
                mma16816(oacc[2*p],   Ph[kc], vl[0], vl[1]);
                mma16816(oacc[2*p+1], Ph[kc], vl[2], vl[3]);
            }
        }
        __syncthreads();
    }

    const float iA = 1.f / l0, iB = 1.f / l1;
    const int rA = lane >> 2;
    const size_t grA = (rowbase + (size_t)qt * 64 + wm * 16 + rA) * 1024 + hoff;
    const size_t grB = grA + 8 * 1024;
#pragma unroll
    for (int nt = 0; nt < 8; nt++) {
        const int c = nt * 8 + (lane & 3) * 2;
        float a0 = oacc[nt][0] * iA, a1 = oacc[nt][1] * iA;
        float b0 = oacc[nt][2] * iB, b1 = oacc[nt][3] * iB;
        *(uint32_t*)(O2 + grA + c)       = pack2hi(a0, a1);
        *(uint32_t*)(O2 + OPL + grA + c) = pack2lo(a0, a1);
        *(uint32_t*)(O2 + grB + c)       = pack2hi(b0, b1);
        *(uint32_t*)(O2 + OPL + grB + c) = pack2lo(b0, b1);
    }
}

// ================= host orchestration =========================================
static inline void pack_launch(const float* src, unsigned short* dst, size_t nelem) {
    int n8 = (int)(nelem / 8);
    pack_k<<<(n8 + 255) / 256, 256>>>(src, dst, n8, nelem);
}

extern "C" void kernel_launch(void* const* d_in, const int* in_sizes, int n_in,
                              void* d_out, int out_size)
{
    const float* x        = (const float*)d_in[0];
    const float* feature  = (const float*)d_in[1];
    const float* ln1_g    = (const float*)d_in[2];
    const float* ln1_b    = (const float*)d_in[3];
    const float* ln2_g    = (const float*)d_in[4];
    const float* ln2_b    = (const float*)d_in[5];
    const float* sa_qkv_w = (const float*)d_in[6];
    const float* sa_qkv_b = (const float*)d_in[7];
    const float* sa_qkv_a = (const float*)d_in[8];
    const float* sa_qkv_lb= (const float*)d_in[9];
    const float* sa_pr_w  = (const float*)d_in[10];
    const float* sa_pr_b  = (const float*)d_in[11];
    const float* sa_pr_a  = (const float*)d_in[12];
    const float* sa_pr_lb = (const float*)d_in[13];
    const float* ca_q_w   = (const float*)d_in[14];
    const float* ca_q_b   = (const float*)d_in[15];
    const float* ca_q_a   = (const float*)d_in[16];
    const float* ca_q_lb  = (const float*)d_in[17];
    const float* ca_kv_w  = (const float*)d_in[18];
    const float* ca_kv_b  = (const float*)d_in[19];
    const float* ca_kv_a  = (const float*)d_in[20];
    const float* ca_kv_lb = (const float*)d_in[21];
    const float* ca_pr_w  = (const float*)d_in[22];
    const float* ca_pr_b  = (const float*)d_in[23];
    const float* ca_pr_a  = (const float*)d_in[24];
    const float* ca_pr_lb = (const float*)d_in[25];
    const float* fc_w     = (const float*)d_in[26];
    const float* fc_b     = (const float*)d_in[27];
    const float* pr_w     = (const float*)d_in[28];
    const float* pr_b     = (const float*)d_in[29];

    float* xo = (float*)d_out;

    float* t;
    unsigned short *h2, *o2, *f2, *qkv2, *kv2, *mlp2;
    unsigned short *wqkv2, *wsap2, *wcaq2, *wcakv2, *wcap2, *wfc2, *wpr2;
    cudaGetSymbolAddress((void**)&t,     g_t);
    cudaGetSymbolAddress((void**)&h2,    g_h2);
    cudaGetSymbolAddress((void**)&o2,    g_o2);
    cudaGetSymbolAddress((void**)&f2,    g_f2);
    cudaGetSymbolAddress((void**)&qkv2,  g_qkv2);
    cudaGetSymbolAddress((void**)&kv2,   g_kv2);
    cudaGetSymbolAddress((void**)&mlp2,  g_mlp2);
    cudaGetSymbolAddress((void**)&wqkv2, g_wqkv2);
    cudaGetSymbolAddress((void**)&wsap2, g_wsap2);
    cudaGetSymbolAddress((void**)&wcaq2, g_wcaq2);
    cudaGetSymbolAddress((void**)&wcakv2,g_wcakv2);
    cudaGetSymbolAddress((void**)&wcap2, g_wcap2);
    cudaGetSymbolAddress((void**)&wfc2,  g_wfc2);
    cudaGetSymbolAddress((void**)&wpr2,  g_wpr2);

    cudaFuncSetAttribute(gemm_bf16, cudaFuncAttributeMaxDynamicSharedMemorySize,
                         GEMM_SMEM);
    cudaFuncSetAttribute(attn_k, cudaFuncAttributeMaxDynamicSharedMemorySize,
                         ATTN_SMEM);

    cudaMemcpyAsync(xo, x, (size_t)MROWS * CDIM * sizeof(float),
                    cudaMemcpyDeviceToDevice);

    const size_t PC = (size_t)CDIM * CDIM;
    const size_t PA = (size_t)MROWS * CDIM;

    // ---- self attention ----
    pack_launch(sa_qkv_w, wqkv2, 3 * PC);
    ln_k    <<<MROWS, 256>>>(xo, ln1_g, ln1_b, h2, sa_qkv_a, t);   // fused lora t
    gemm_bf16<<<dim3(24, 32), 256, GEMM_SMEM>>>(
        h2, PA, wqkv2, 3 * PC, sa_qkv_b, t, sa_qkv_lb,
        nullptr, qkv2, 3 * PA, MROWS, 3072, 1024, F_LORA | F_PACK);
    attn_k  <<<dim3(16, 64), 128, ATTN_SMEM>>>(
        qkv2, 3072, 3 * PA, qkv2 + 1024, 3072, 3 * PA, qkv2 + 2048, 3072, 3 * PA, o2);
    pack_launch(sa_pr_w, wsap2, PC);
    lora_tp_k<<<MROWS, 256>>>(o2, sa_pr_a, t);
    gemm_bf16<<<dim3(8, 32), 256, GEMM_SMEM>>>(
        o2, PA, wsap2, PC, sa_pr_b, t, sa_pr_lb,
        xo, xo, 0, MROWS, 1024, 1024, F_LORA | F_RES);

    // ---- cross attention (tri(T,S) == causal since T==S) ----
    ln_k    <<<MROWS, 256>>>(xo, ln1_g, ln1_b, h2, ca_q_a, t);     // fused lora t
    pack_launch(ca_q_w, wcaq2, PC);
    gemm_bf16<<<dim3(8, 32), 256, GEMM_SMEM>>>(
        h2, PA, wcaq2, PC, ca_q_b, t, ca_q_lb,
        nullptr, qkv2, PA, MROWS, 1024, 1024, F_LORA | F_PACK);
    pack_launch(ca_kv_w, wcakv2, 2 * PC);
    pack_lora_k<<<MROWS, 256>>>(feature, f2, PA, ca_kv_a, t);      // fused pack+lora
    gemm_bf16<<<dim3(16, 32), 256, GEMM_SMEM>>>(
        f2, PA, wcakv2, 2 * PC, ca_kv_b, t, ca_kv_lb,
        nullptr, kv2, 2 * PA, MROWS, 2048, 1024, F_LORA | F_PACK);
    attn_k  <<<dim3(16, 64), 128, ATTN_SMEM>>>(
        qkv2, 1024, PA, kv2, 2048, 2 * PA, kv2 + 1024, 2048, 2 * PA, o2);
    lora_tp_k<<<MROWS, 256>>>(o2, ca_pr_a, t);
    pack_launch(ca_pr_w, wcap2, PC);
    gemm_bf16<<<dim3(8, 32), 256, GEMM_SMEM>>>(
        o2, PA, wcap2, PC, ca_pr_b, t, ca_pr_lb,
        xo, xo, 0, MROWS, 1024, 1024, F_LORA | F_RES);

    // ---- MLP ----
    ln_k    <<<MROWS, 256>>>(xo, ln2_g, ln2_b, h2, nullptr, nullptr);
    pack_launch(fc_w, wfc2, 4 * PC);
    gemm_bf16<<<dim3(32, 32), 256, GEMM_SMEM>>>(
        h2, PA, wfc2, 4 * PC, fc_b, nullptr, nullptr,
        nullptr, mlp2, 4 * PA, MROWS, 4096, 1024, F_GELU | F_PACK);
    pack_launch(pr_w, wpr2, 4 * PC);
    gemm_bf16<<<dim3(8, 32), 256, GEMM_SMEM>>>(
        mlp2, 4 * PA, wpr2, 4 * PC, pr_b, nullptr, nullptr,
        xo, xo, 0, MROWS, 1024, 4096, F_RES);
}

// round 15
// speedup vs baseline: 2.0306x; 1.3262x over previous
#include <cuda_runtime.h>
#include <cuda_fp16.h>
#include <cstdint>

// ================= scratch (device globals; allocation-free) ==================
#define MROWS 4096
#define CDIM  1024

__device__ float g_t  [MROWS * 16];
__device__ unsigned short g_h2  [(size_t)2 * MROWS * CDIM];
__device__ unsigned short g_o2  [(size_t)2 * MROWS * CDIM];
__device__ unsigned short g_f2  [(size_t)2 * MROWS * CDIM];
__device__ unsigned short g_qkv2[(size_t)2 * MROWS * 3 * CDIM];
__device__ unsigned short g_kv2 [(size_t)2 * MROWS * 2 * CDIM];
__device__ unsigned short g_mlp2[(size_t)2 * MROWS * 4 * CDIM];
__device__ unsigned short g_wqkv2 [(size_t)2 * 3 * CDIM * CDIM];
__device__ unsigned short g_wsap2 [(size_t)2 * CDIM * CDIM];
__device__ unsigned short g_wcaq2 [(size_t)2 * CDIM * CDIM];
__device__ unsigned short g_wcakv2[(size_t)2 * 2 * CDIM * CDIM];
__device__ unsigned short g_wcap2 [(size_t)2 * CDIM * CDIM];
__device__ unsigned short g_wfc2  [(size_t)2 * 4 * CDIM * CDIM];
__device__ unsigned short g_wpr2  [(size_t)2 * CDIM * 4 * CDIM];

static const int F_LORA = 1, F_GELU = 2, F_RES = 4, F_PACK = 8;

// ================= helpers ====================================================
__device__ __forceinline__ uint32_t smem_u32(const void* p) {
    uint32_t a;
    asm("{ .reg .u64 t; cvta.to.shared.u64 t, %1; cvt.u32.u64 %0, t; }"
        : "=r"(a) : "l"(p));
    return a;
}
__device__ __forceinline__ void ldmatrix_x4(uint32_t* r, uint32_t addr) {
    asm volatile("ldmatrix.sync.aligned.m8n8.x4.shared.b16 {%0,%1,%2,%3}, [%4];"
        : "=r"(r[0]), "=r"(r[1]), "=r"(r[2]), "=r"(r[3]) : "r"(addr));
}
__device__ __forceinline__ void ldmatrix_x4_t(uint32_t* r, uint32_t addr) {
    asm volatile("ldmatrix.sync.aligned.m8n8.x4.trans.shared.b16 {%0,%1,%2,%3}, [%4];"
        : "=r"(r[0]), "=r"(r[1]), "=r"(r[2]), "=r"(r[3]) : "r"(addr));
}
__device__ __forceinline__ void mma16816(float* c, const uint32_t* a,
                                         uint32_t b0, uint32_t b1) {
    asm volatile("mma.sync.aligned.m16n8k16.row.col.f32.f16.f16.f32 "
        "{%0,%1,%2,%3}, {%4,%5,%6,%7}, {%8,%9}, {%0,%1,%2,%3};"
        : "+f"(c[0]), "+f"(c[1]), "+f"(c[2]), "+f"(c[3])
        : "r"(a[0]), "r"(a[1]), "r"(a[2]), "r"(a[3]), "r"(b0), "r"(b1));
}
__device__ __forceinline__ uint32_t pack2hi(float a, float b) {
    return (uint32_t)__half_as_ushort(__float2half(a))
         | ((uint32_t)__half_as_ushort(__float2half(b)) << 16);
}
__device__ __forceinline__ uint32_t pack2lo(float a, float b) {
    float ra = a - __half2float(__float2half(a));
    float rb = b - __half2float(__float2half(b));
    return (uint32_t)__half_as_ushort(__float2half(ra))
         | ((uint32_t)__half_as_ushort(__float2half(rb)) << 16);
}
__device__ __forceinline__ float up2f(unsigned short u) {
    return __half2float(__ushort_as_half(u));
}
#define CP_ASYNC16(dst, src) \
    asm volatile("cp.async.cg.shared.global [%0], [%1], 16;" \
        :: "r"(dst), "l"(src) : "memory")
#define CP_COMMIT() asm volatile("cp.async.commit_group;" ::: "memory")

// ================= pack: fp32 -> hi plane + lo plane ==========================
__global__ __launch_bounds__(256) void pack_k(const float* __restrict__ X,
                                              unsigned short* __restrict__ Y,
                                              int n8, size_t plane)
{
    int g = blockIdx.x * 256 + threadIdx.x;
    if (g >= n8) return;
    float4 v0 = ((const float4*)X)[g * 2];
    float4 v1 = ((const float4*)X)[g * 2 + 1];
    uint4 hi, lo;
    hi.x = pack2hi(v0.x, v0.y); lo.x = pack2lo(v0.x, v0.y);
    hi.y = pack2hi(v0.z, v0.w); lo.y = pack2lo(v0.z, v0.w);
    hi.z = pack2hi(v1.x, v1.y); lo.z = pack2lo(v1.x, v1.y);
    hi.w = pack2hi(v1.z, v1.w); lo.w = pack2lo(v1.z, v1.w);
    *(uint4*)(Y + (size_t)g * 8)         = hi;
    *(uint4*)(Y + plane + (size_t)g * 8) = lo;
}

// ======= pack rows + fused lora t = x @ A^T (one block per row) ===============
__global__ __launch_bounds__(256) void pack_lora_k(const float* __restrict__ X,
                                                   unsigned short* __restrict__ Y,
                                                   size_t plane,
                                                   const float* __restrict__ Aw,
                                                   float* __restrict__ T)
{
    const int row = blockIdx.x, t = threadIdx.x;
    const float* xr = X + (size_t)row * 1024;
    float4 v = ((const float4*)xr)[t];
    *(uint2*)(Y + (size_t)row * 1024 + t * 4) =
        make_uint2(pack2hi(v.x, v.y), pack2hi(v.z, v.w));
    *(uint2*)(Y + plane + (size_t)row * 1024 + t * 4) =
        make_uint2(pack2lo(v.x, v.y), pack2lo(v.z, v.w));

    __shared__ float lred[8][16];
    const int lane = t & 31, warp = t >> 5;
    float acc[16];
#pragma unroll
    for (int r = 0; r < 16; r++) {
        float4 av = *(const float4*)&Aw[r * 1024 + t * 4];
        acc[r] = v.x * av.x + v.y * av.y + v.z * av.z + v.w * av.w;
    }
#pragma unroll
    for (int r = 0; r < 16; r++) {
        float vv = acc[r];
#pragma unroll
        for (int o = 16; o > 0; o >>= 1)
            vv += __shfl_down_sync(0xffffffffu, vv, o);
        if (lane == 0) lred[warp][r] = vv;
    }
    __syncthreads();
    if (t < 16) {
        float s = 0.f;
#pragma unroll
        for (int w = 0; w < 8; w++) s += lred[w][t];
        T[(size_t)row * 16 + t] = s;
    }
}

// ====== LayerNorm -> packed planes, with optional fused lora t = y @ A^T ======
__global__ __launch_bounds__(256) void ln_k(const float* __restrict__ X,
                                            const float* __restrict__ gw,
                                            const float* __restrict__ bw,
                                            unsigned short* __restrict__ O2,
                                            const float* __restrict__ Aw,
                                            float* __restrict__ T)
{
    const size_t PL = (size_t)MROWS * CDIM;
    const int row = blockIdx.x, t = threadIdx.x;
    const float* xr = X + (size_t)row * 1024;
    float4 v = ((const float4*)xr)[t];
    float loc[4] = {v.x, v.y, v.z, v.w};
    float sum = loc[0] + loc[1] + loc[2] + loc[3];
    __shared__ float red[256];
    __shared__ float lred[8][16];
    red[t] = sum; __syncthreads();
#pragma unroll
    for (int o = 128; o > 0; o >>= 1) { if (t < o) red[t] += red[t + o]; __syncthreads(); }
    const float mean = red[0] * (1.f / 1024.f);
    __syncthreads();
    float vs = 0.f;
#pragma unroll
    for (int i = 0; i < 4; i++) { float d = loc[i] - mean; vs += d * d; }
    red[t] = vs; __syncthreads();
#pragma unroll
    for (int o = 128; o > 0; o >>= 1) { if (t < o) red[t] += red[t + o]; __syncthreads(); }
    const float inv = rsqrtf(red[0] * (1.f / 1024.f) + 1e-5f);
    float4 gv = ((const float4*)gw)[t];
    float4 bv = ((const float4*)bw)[t];
    float y[4];
    y[0] = (loc[0] - mean) * inv * gv.x + bv.x;
    y[1] = (loc[1] - mean) * inv * gv.y + bv.y;
    y[2] = (loc[2] - mean) * inv * gv.z + bv.z;
    y[3] = (loc[3] - mean) * inv * gv.w + bv.w;
    *(uint2*)(O2 + (size_t)row * 1024 + t * 4) =
        make_uint2(pack2hi(y[0], y[1]), pack2hi(y[2], y[3]));
    *(uint2*)(O2 + PL + (size_t)row * 1024 + t * 4) =
        make_uint2(pack2lo(y[0], y[1]), pack2lo(y[2], y[3]));

    if (Aw != nullptr) {
        const int lane = t & 31, warp = t >> 5;
        float acc[16];
#pragma unroll
        for (int r = 0; r < 16; r++) {
            float4 av = *(const float4*)&Aw[r * 1024 + t * 4];
            acc[r] = y[0] * av.x + y[1] * av.y + y[2] * av.z + y[3] * av.w;
        }
#pragma unroll
        for (int r = 0; r < 16; r++) {
            float vv = acc[r];
#pragma unroll
            for (int o = 16; o > 0; o >>= 1)
                vv += __shfl_down_sync(0xffffffffu, vv, o);
            if (lane == 0) lred[warp][r] = vv;
        }
        __syncthreads();
        if (t < 16) {
            float s = 0.f;
#pragma unroll
            for (int w = 0; w < 8; w++) s += lred[w][t];
            T[(size_t)row * 16 + t] = s;
        }
    }
}

// ================= lora t: packed hi/lo input variant =========================
__global__ __launch_bounds__(256) void lora_tp_k(const unsigned short* __restrict__ X2,
                                                 const float* __restrict__ Aw,
                                                 float* __restrict__ T)
{
    const size_t PL = (size_t)MROWS * CDIM;
    const int row = blockIdx.x;
    const unsigned short* xh = X2 + (size_t)row * 1024;
    const unsigned short* xl = xh + PL;
    float acc[16];
#pragma unroll
    for (int r = 0; r < 16; r++) acc[r] = 0.f;
    for (int k = threadIdx.x; k < 1024; k += 256) {
        float xv = up2f(xh[k]) + up2f(xl[k]);
#pragma unroll
        for (int r = 0; r < 16; r++) acc[r] += xv * Aw[r * 1024 + k];
    }
    __shared__ float red[8][16];
    const int lane = threadIdx.x & 31, warp = threadIdx.x >> 5;
#pragma unroll
    for (int r = 0; r < 16; r++) {
        float v = acc[r];
#pragma unroll
        for (int o = 16; o > 0; o >>= 1) v += __shfl_down_sync(0xffffffffu, v, o);
        if (lane == 0) red[warp][r] = v;
    }
    __syncthreads();
    if (threadIdx.x < 16) {
        float s = 0.f;
#pragma unroll
        for (int w = 0; w < 8; w++) s += red[w][threadIdx.x];
        T[(size_t)row * 16 + threadIdx.x] = s;
    }
}

// == fp16 HMMA GEMM: A split 2-plane, B hi-only, 2-pass (exact A x fp16(B)) ====
#define NSTAGE 3
#define STG_B 32768
#define GEMM_SMEM (NSTAGE * STG_B)

__global__ __launch_bounds__(256, 2) void gemm_fp16(
    const unsigned short* __restrict__ A, size_t aPl,
    const unsigned short* __restrict__ B,
    const float* __restrict__ bias,
    const float* __restrict__ lT, const float* __restrict__ lB,
    const float* __restrict__ res,
    void* __restrict__ Cout, size_t cPl,
    int M, int N, int K, int flags)
{
    extern __shared__ char smem[];
    const uint32_t sb0 = smem_u32(smem);
    const int tid = threadIdx.x, lane = tid & 31, wid = tid >> 5;
    const int wm = wid >> 2, wn = wid & 3;
    const int bm = blockIdx.y * 128, bn = blockIdx.x * 128;
    const int NC = K >> 5;

    const int lr = tid & 127, side = tid >> 7;
    const unsigned short* gh = side ? B + (size_t)(bn + lr) * K
                                    : A + (size_t)(bm + lr) * K;
    const unsigned short* gl = gh + aPl;          // only valid for side==0
    uint32_t dst[8];
#pragma unroll
    for (int c = 0; c < 8; c++)
        dst[c] = (uint32_t)side * 16384u + (uint32_t)lr * 128u
               + (uint32_t)((c ^ (lr & 7)) << 4);

    float acc[4][4][4];
#pragma unroll
    for (int i = 0; i < 4; i++)
#pragma unroll
        for (int j = 0; j < 4; j++)
#pragma unroll
            for (int q = 0; q < 4; q++) acc[i][j][q] = 0.f;

    auto issue = [&](int s, int kt) {
        uint32_t st = sb0 + s * STG_B;
        const unsigned short* ph = gh + kt * 32;
#pragma unroll
        for (int c = 0; c < 4; c++)
            CP_ASYNC16(st + dst[c], ph + c * 8);
        if (!side) {
            const unsigned short* pl = gl + kt * 32;
#pragma unroll
            for (int c = 4; c < 8; c++)
                CP_ASYNC16(st + dst[c], pl + (c - 4) * 8);
        }
    };

    issue(0, 0); CP_COMMIT();
    issue(1, 1); CP_COMMIT();

    int scur = 0, snext = 2;
    for (int kt = 0; kt < NC; kt++) {
        asm volatile("cp.async.wait_group 1;" ::: "memory");
        __syncthreads();
        if (kt + 2 < NC) { issue(snext, kt + 2); CP_COMMIT();
                           snext = (snext == 2) ? 0 : snext + 1; }

        const uint32_t st = sb0 + scur * STG_B;
        scur = (scur == 2) ? 0 : scur + 1;
#pragma unroll
        for (int ks = 0; ks < 2; ks++) {
            uint32_t ah[4][4], al[4][4];
#pragma unroll
            for (int i = 0; i < 4; i++) {
                const int r = wm * 64 + i * 16 + (lane & 15);
                const int ch = ks * 2 + (lane >> 4);
                ldmatrix_x4(ah[i], st + r * 128 + ((ch ^ (r & 7)) << 4));
                ldmatrix_x4(al[i], st + r * 128 + (((ch + 4) ^ (r & 7)) << 4));
            }
#pragma unroll
            for (int jj = 0; jj < 2; jj++) {
                const int r = wn * 32 + jj * 16 + (lane & 7) + ((lane >> 4) << 3);
                const int ch = ks * 2 + ((lane >> 3) & 1);
                uint32_t bh[4];
                ldmatrix_x4(bh, st + 16384 + r * 128 + ((ch ^ (r & 7)) << 4));
#pragma unroll
                for (int i = 0; i < 4; i++) {
                    mma16816(acc[i][2 * jj],     ah[i], bh[0], bh[1]);
                    mma16816(acc[i][2 * jj + 1], ah[i], bh[2], bh[3]);
                }
#pragma unroll
                for (int i = 0; i < 4; i++) {
                    mma16816(acc[i][2 * jj],     al[i], bh[0], bh[1]);
                    mma16816(acc[i][2 * jj + 1], al[i], bh[2], bh[3]);
                }
            }
        }
    }
    asm volatile("cp.async.wait_group 0;" ::: "memory");
    __syncthreads();

    float* sLT = (float*)smem;
    float* sLB = (float*)(smem + 8192);
    if (flags & F_LORA) {
        if (tid < 128) {
#pragma unroll
            for (int q = 0; q < 4; q++)
                ((float4*)&sLT[tid * 16])[q] = ((const float4*)&lT[(size_t)(bm + tid) * 16])[q];
        } else {
            int r = tid - 128;
#pragma unroll
            for (int q = 0; q < 4; q++)
                ((float4*)&sLB[r * 16])[q] = ((const float4*)&lB[(size_t)(bn + r) * 16])[q];
        }
        __syncthreads();
    }

#pragma unroll
    for (int i = 0; i < 4; i++) {
#pragma unroll
        for (int j = 0; j < 4; j++) {
            const int ml = wm * 64 + i * 16 + (lane >> 2);
            const int nl = wn * 32 + j * 8 + (lane & 3) * 2;
            float v[4] = {acc[i][j][0], acc[i][j][1], acc[i][j][2], acc[i][j][3]};
            const float b0 = bias[bn + nl], b1 = bias[bn + nl + 1];
            v[0] += b0; v[1] += b1; v[2] += b0; v[3] += b1;
            if (flags & F_LORA) {
                float s00 = 0, s01 = 0, s10 = 0, s11 = 0;
#pragma unroll
                for (int r = 0; r < 16; r++) {
                    float t0 = sLT[ml * 16 + r], t1 = sLT[(ml + 8) * 16 + r];
                    float u0 = sLB[nl * 16 + r], u1 = sLB[(nl + 1) * 16 + r];
                    s00 += t0 * u0; s01 += t0 * u1; s10 += t1 * u0; s11 += t1 * u1;
                }
                v[0] += s00 * 0.0625f; v[1] += s01 * 0.0625f;
                v[2] += s10 * 0.0625f; v[3] += s11 * 0.0625f;
            }
            if (flags & F_GELU) {
#pragma unroll
                for (int q = 0; q < 4; q++) {
                    float u = v[q];
                    float c2 = 0.7978845608028654f * (u + 0.044715f * u * u * u);
                    v[q] = 0.5f * u * (1.0f + tanhf(c2));
                }
            }
            const int m0 = bm + ml, m1 = m0 + 8, n0 = bn + nl;
            if (flags & F_RES) {
                float2 r0 = *(const float2*)&res[(size_t)m0 * N + n0];
                float2 r1 = *(const float2*)&res[(size_t)m1 * N + n0];
                v[0] += r0.x; v[1] += r0.y; v[2] += r1.x; v[3] += r1.y;
            }
            if (flags & F_PACK) {
                unsigned short* Y = (unsigned short*)Cout;
                *(uint32_t*)(Y + (size_t)m0 * N + n0)       = pack2hi(v[0], v[1]);
                *(uint32_t*)(Y + cPl + (size_t)m0 * N + n0) = pack2lo(v[0], v[1]);
                *(uint32_t*)(Y + (size_t)m1 * N + n0)       = pack2hi(v[2], v[3]);
                *(uint32_t*)(Y + cPl + (size_t)m1 * N + n0) = pack2lo(v[2], v[3]);
            } else {
                float* C = (float*)Cout;
                *(float2*)&C[(size_t)m0 * N + n0] = make_float2(v[0], v[1]);
                *(float2*)&C[(size_t)m1 * N + n0] = make_float2(v[2], v[3]);
            }
        }
    }
}

// ====== HMMA split-fp16 flash attention (packed I/O, 3-pass as before) ========
#define ATTN_SMEM 65536

__global__ __launch_bounds__(128) void attn_k(
    const unsigned short* __restrict__ Qp, int qs, size_t qPl,
    const unsigned short* __restrict__ Kp, int ks, size_t kPl,
    const unsigned short* __restrict__ Vp, int vs, size_t vPl,
    unsigned short* __restrict__ O2)
{
    extern __shared__ char smem[];
    const uint32_t sb0 = smem_u32(smem);
    const size_t OPL = (size_t)MROWS * CDIM;
    const int qt = gridDim.x - 1 - blockIdx.x;
    const int b = blockIdx.y >> 4, h = blockIdx.y & 15;
    const int tid = threadIdx.x, lane = tid & 31, wm = tid >> 5;
    const size_t rowbase = (size_t)b * 1024;
    const int hoff = h * 64;

    const int r = tid >> 1, cg = (tid & 1) * 4;
    uint32_t dstc[4];
#pragma unroll
    for (int c = 0; c < 4; c++)
        dstc[c] = (uint32_t)r * 128u + (uint32_t)(((cg + c) ^ (r & 7)) << 4);

    {
        const unsigned short* qh = Qp + (rowbase + (size_t)qt * 64 + r) * qs + hoff;
        const unsigned short* ql = qh + qPl;
#pragma unroll
        for (int c = 0; c < 4; c++) {
            CP_ASYNC16(sb0 + dstc[c],        qh + (cg + c) * 8);
            CP_ASYNC16(sb0 + 8192 + dstc[c], ql + (cg + c) * 8);
        }
        CP_COMMIT();
        asm volatile("cp.async.wait_group 0;" ::: "memory");
    }
    __syncthreads();

    uint32_t Qh[4][4], Ql[4][4];
    {
        const int j = lane >> 3, rr2 = lane & 7;
        const int row = wm * 16 + ((j & 1) << 3) + rr2;
#pragma unroll
        for (int kc = 0; kc < 4; kc++) {
            const int col = kc * 16 + ((j >> 1) << 3);
            const uint32_t off = (uint32_t)row * 128 + ((((uint32_t)col >> 3) ^ (row & 7)) << 4);
            ldmatrix_x4(Qh[kc], sb0 + off);
            ldmatrix_x4(Ql[kc], sb0 + 8192 + off);
        }
    }
    __syncthreads();

    auto issue_kv = [&](int stage, int jt) {
        const uint32_t st = sb0 + stage * 32768;
        const size_t grow = rowbase + (size_t)jt * 64 + r;
        const unsigned short* kh = Kp + grow * ks + hoff;
        const unsigned short* vh = Vp + grow * vs + hoff;
#pragma unroll
        for (int c = 0; c < 4; c++) {
            CP_ASYNC16(st + dstc[c],         kh + (cg + c) * 8);
            CP_ASYNC16(st + 8192 + dstc[c],  kh + kPl + (cg + c) * 8);
            CP_ASYNC16(st + 16384 + dstc[c], vh + (cg + c) * 8);
            CP_ASYNC16(st + 24576 + dstc[c], vh + vPl + (cg + c) * 8);
        }
    };

    float oacc[8][4];
#pragma unroll
    for (int nt = 0; nt < 8; nt++)
#pragma unroll
        for (int q = 0; q < 4; q++) oacc[nt][q] = 0.f;
    float m0v = -1e30f, m1v = -1e30f, l0 = 0.f, l1 = 0.f;

    const int jj = lane >> 3, rr2 = lane & 7;
    const int nTiles = qt + 1;

    issue_kv(0, 0);
    CP_COMMIT();

    for (int jt = 0; jt < nTiles; jt++) {
        if (jt + 1 < nTiles) { issue_kv((jt + 1) & 1, jt + 1); CP_COMMIT(); }
        if (jt + 1 < nTiles) asm volatile("cp.async.wait_group 1;" ::: "memory");
        else                 asm volatile("cp.async.wait_group 0;" ::: "memory");
        __syncthreads();
        const uint32_t st = sb0 + (jt & 1) * 32768;

        float sacc[8][4];
#pragma unroll
        for (int nt = 0; nt < 8; nt++)
#pragma unroll
            for (int q = 0; q < 4; q++) sacc[nt][q] = 0.f;

#pragma unroll
        for (int kc = 0; kc < 4; kc++) {
#pragma unroll
            for (int p = 0; p < 4; p++) {
                const int krow = p * 16 + ((jj >> 1) << 3) + rr2;
                const int kcol = kc * 16 + ((jj & 1) << 3);
                const uint32_t off = (uint32_t)krow * 128
                                   + ((((uint32_t)kcol >> 3) ^ (krow & 7)) << 4);
                uint32_t bh[4], bl[4];
                ldmatrix_x4(bh, st + off);
                mma16816(sacc[2*p],   Qh[kc], bh[0], bh[1]);
                mma16816(sacc[2*p+1], Qh[kc], bh[2], bh[3]);
                mma16816(sacc[2*p],   Ql[kc], bh[0], bh[1]);
                mma16816(sacc[2*p+1], Ql[kc], bh[2], bh[3]);
                ldmatrix_x4(bl, st + 8192 + off);
                mma16816(sacc[2*p],   Qh[kc], bl[0], bl[1]);
                mma16816(sacc[2*p+1], Qh[kc], bl[2], bl[3]);
            }
        }
#pragma unroll
        for (int nt = 0; nt < 8; nt++)
#pragma unroll
            for (int q = 0; q < 4; q++) sacc[nt][q] *= 0.125f;

        const int rA = lane >> 2;
        if (jt == qt) {
            const int gA = wm * 16 + rA, gB = gA + 8;
#pragma unroll
            for (int nt = 0; nt < 8; nt++) {
                const int c = nt * 8 + (lane & 3) * 2;
                if (c     > gA) sacc[nt][0] = -1e30f;
                if (c + 1 > gA) sacc[nt][1] = -1e30f;
                if (c     > gB) sacc[nt][2] = -1e30f;
                if (c + 1 > gB) sacc[nt][3] = -1e30f;
            }
        }
        float mxA = -1e30f, mxB = -1e30f;
#pragma unroll
        for (int nt = 0; nt < 8; nt++) {
            mxA = fmaxf(mxA, fmaxf(sacc[nt][0], sacc[nt][1]));
            mxB = fmaxf(mxB, fmaxf(sacc[nt][2], sacc[nt][3]));
        }
        mxA = fmaxf(mxA, __shfl_xor_sync(0xffffffffu, mxA, 1));
        mxA = fmaxf(mxA, __shfl_xor_sync(0xffffffffu, mxA, 2));
        mxB = fmaxf(mxB, __shfl_xor_sync(0xffffffffu, mxB, 1));
        mxB = fmaxf(mxB, __shfl_xor_sync(0xffffffffu, mxB, 2));
        const float mnA = fmaxf(m0v, mxA), mnB = fmaxf(m1v, mxB);
        const float aA = __expf(m0v - mnA), aB = __expf(m1v - mnB);
        float sA = 0.f, sB = 0.f;
#pragma unroll
        for (int nt = 0; nt < 8; nt++) {
            float p0 = __expf(sacc[nt][0] - mnA);
            float p1 = __expf(sacc[nt][1] - mnA);
            float p2 = __expf(sacc[nt][2] - mnB);
            float p3 = __expf(sacc[nt][3] - mnB);
            sacc[nt][0] = p0; sacc[nt][1] = p1; sacc[nt][2] = p2; sacc[nt][3] = p3;
            sA += p0 + p1; sB += p2 + p3;
        }
        sA += __shfl_xor_sync(0xffffffffu, sA, 1);
        sA += __shfl_xor_sync(0xffffffffu, sA, 2);
        sB += __shfl_xor_sync(0xffffffffu, sB, 1);
        sB += __shfl_xor_sync(0xffffffffu, sB, 2);
        l0 = l0 * aA + sA; l1 = l1 * aB + sB;
        m0v = mnA; m1v = mnB;
#pragma unroll
        for (int nt = 0; nt < 8; nt++) {
            oacc[nt][0] *= aA; oacc[nt][1] *= aA;
            oacc[nt][2] *= aB; oacc[nt][3] *= aB;
        }

        uint32_t Ph[4][4], Pl[4][4];
#pragma unroll
        for (int kc = 0; kc < 4; kc++) {
            float* t0 = sacc[2 * kc];
            float* t1 = sacc[2 * kc + 1];
            Ph[kc][0] = pack2hi(t0[0], t0[1]); Pl[kc][0] = pack2lo(t0[0], t0[1]);
            Ph[kc][1] = pack2hi(t0[2], t0[3]); Pl[kc][1] = pack2lo(t0[2], t0[3]);
            Ph[kc][2] = pack2hi(t1[0], t1[1]); Pl[kc][2] = pack2lo(t1[0], t1[1]);
            Ph[kc][3] = pack2hi(t1[2], t1[3]); Pl[kc][3] = pack2lo(t1[2], t1[3]);
        }

#pragma unroll
        for (int kc = 0; kc < 4; kc++) {
            const int vrow = kc * 16 + ((jj & 1) << 3) + rr2;
#pragma unroll
            for (int p = 0; p < 4; p++) {
                const int vcol = p * 16 + ((jj >> 1) << 3);
                const uint32_t off = (uint32_t)vrow * 128
                                   + ((((uint32_t)vcol >> 3) ^ (vrow & 7)) << 4);
                uint32_t vh[4], vl[4];
                ldmatrix_x4_t(vh, st + 16384 + off);
                mma16816(oacc[2*p],   Ph[kc], vh[0], vh[1]);
                mma16816(oacc[2*p+1], Ph[kc], vh[2], vh[3]);
                mma16816(oacc[2*p],   Pl[kc], vh[0], vh[1]);
                mma16816(oacc[2*p+1], Pl[kc], vh[2], vh[3]);
                ldmatrix_x4_t(vl, st + 24576 + off);
                mma16816(oacc[2*p],   Ph[kc], vl[0], vl[1]);
                mma16816(oacc[2*p+1], Ph[kc], vl[2], vl[3]);
            }
        }
        __syncthreads();
    }

    const float iA = 1.f / l0, iB = 1.f / l1;
    const int rA = lane >> 2;
    const size_t grA = (rowbase + (size_t)qt * 64 + wm * 16 + rA) * 1024 + hoff;
    const size_t grB = grA + 8 * 1024;
#pragma unroll
    for (int nt = 0; nt < 8; nt++) {
        const int c = nt * 8 + (lane & 3) * 2;
        float a0 = oacc[nt][0] * iA, a1 = oacc[nt][1] * iA;
        float b0 = oacc[nt][2] * iB, b1 = oacc[nt][3] * iB;
        *(uint32_t*)(O2 + grA + c)       = pack2hi(a0, a1);
        *(uint32_t*)(O2 + OPL + grA + c) = pack2lo(a0, a1);
        *(uint32_t*)(O2 + grB + c)       = pack2hi(b0, b1);
        *(uint32_t*)(O2 + OPL + grB + c) = pack2lo(b0, b1);
    }
}

// ================= host orchestration =========================================
static inline void pack_launch(const float* src, unsigned short* dst, size_t nelem) {
    int n8 = (int)(nelem / 8);
    pack_k<<<(n8 + 255) / 256, 256>>>(src, dst, n8, nelem);
}

extern "C" void kernel_launch(void* const* d_in, const int* in_sizes, int n_in,
                              void* d_out, int out_size)
{
    const float* x        = (const float*)d_in[0];
    const float* feature  = (const float*)d_in[1];
    const float* ln1_g    = (const float*)d_in[2];
    const float* ln1_b    = (const float*)d_in[3];
    const float* ln2_g    = (const float*)d_in[4];
    const float* ln2_b    = (const float*)d_in[5];
    const float* sa_qkv_w = (const float*)d_in[6];
    const float* sa_qkv_b = (const float*)d_in[7];
    const float* sa_qkv_a = (const float*)d_in[8];
    const float* sa_qkv_lb= (const float*)d_in[9];
    const float* sa_pr_w  = (const float*)d_in[10];
    const float* sa_pr_b  = (const float*)d_in[11];
    const float* sa_pr_a  = (const float*)d_in[12];
    const float* sa_pr_lb = (const float*)d_in[13];
    const float* ca_q_w   = (const float*)d_in[14];
    const float* ca_q_b   = (const float*)d_in[15];
    const float* ca_q_a   = (const float*)d_in[16];
    const float* ca_q_lb  = (const float*)d_in[17];
    const float* ca_kv_w  = (const float*)d_in[18];
    const float* ca_kv_b  = (const float*)d_in[19];
    const float* ca_kv_a  = (const float*)d_in[20];
    const float* ca_kv_lb = (const float*)d_in[21];
    const float* ca_pr_w  = (const float*)d_in[22];
    const float* ca_pr_b  = (const float*)d_in[23];
    const float* ca_pr_a  = (const float*)d_in[24];
    const float* ca_pr_lb = (const float*)d_in[25];
    const float* fc_w     = (const float*)d_in[26];
    const float* fc_b     = (const float*)d_in[27];
    const float* pr_w     = (const float*)d_in[28];
    const float* pr_b     = (const float*)d_in[29];

    float* xo = (float*)d_out;

    float* t;
    unsigned short *h2, *o2, *f2, *qkv2, *kv2, *mlp2;
    unsigned short *wqkv2, *wsap2, *wcaq2, *wcakv2, *wcap2, *wfc2, *wpr2;
    cudaGetSymbolAddress((void**)&t,     g_t);
    cudaGetSymbolAddress((void**)&h2,    g_h2);
    cudaGetSymbolAddress((void**)&o2,    g_o2);
    cudaGetSymbolAddress((void**)&f2,    g_f2);
    cudaGetSymbolAddress((void**)&qkv2,  g_qkv2);
    cudaGetSymbolAddress((void**)&kv2,   g_kv2);
    cudaGetSymbolAddress((void**)&mlp2,  g_mlp2);
    cudaGetSymbolAddress((void**)&wqkv2, g_wqkv2);
    cudaGetSymbolAddress((void**)&wsap2, g_wsap2);
    cudaGetSymbolAddress((void**)&wcaq2, g_wcaq2);
    cudaGetSymbolAddress((void**)&wcakv2,g_wcakv2);
    cudaGetSymbolAddress((void**)&wcap2, g_wcap2);
    cudaGetSymbolAddress((void**)&wfc2,  g_wfc2);
    cudaGetSymbolAddress((void**)&wpr2,  g_wpr2);

    cudaFuncSetAttribute(gemm_fp16, cudaFuncAttributeMaxDynamicSharedMemorySize,
                         GEMM_SMEM);
    cudaFuncSetAttribute(attn_k, cudaFuncAttributeMaxDynamicSharedMemorySize,
                         ATTN_SMEM);

    cudaMemcpyAsync(xo, x, (size_t)MROWS * CDIM * sizeof(float),
                    cudaMemcpyDeviceToDevice);

    const size_t PC = (size_t)CDIM * CDIM;
    const size_t PA = (size_t)MROWS * CDIM;

    // ---- self attention ----
    pack_launch(sa_qkv_w, wqkv2, 3 * PC);
    ln_k    <<<MROWS, 256>>>(xo, ln1_g, ln1_b, h2, sa_qkv_a, t);
    gemm_fp16<<<dim3(24, 32), 256, GEMM_SMEM>>>(
        h2, PA, wqkv2, sa_qkv_b, t, sa_qkv_lb,
        nullptr, qkv2, 3 * PA, MROWS, 3072, 1024, F_LORA | F_PACK);
    attn_k  <<<dim3(16, 64), 128, ATTN_SMEM>>>(
        qkv2, 3072, 3 * PA, qkv2 + 1024, 3072, 3 * PA, qkv2 + 2048, 3072, 3 * PA, o2);
    pack_launch(sa_pr_w, wsap2, PC);
    lora_tp_k<<<MROWS, 256>>>(o2, sa_pr_a, t);
    gemm_fp16<<<dim3(8, 32), 256, GEMM_SMEM>>>(
        o2, PA, wsap2, sa_pr_b, t, sa_pr_lb,
        xo, xo, 0, MROWS, 1024, 1024, F_LORA | F_RES);

    // ---- cross attention (tri(T,S) == causal since T==S) ----
    ln_k    <<<MROWS, 256>>>(xo, ln1_g, ln1_b, h2, ca_q_a, t);
    pack_launch(ca_q_w, wcaq2, PC);
    gemm_fp16<<<dim3(8, 32), 256, GEMM_SMEM>>>(
        h2, PA, wcaq2, ca_q_b, t, ca_q_lb,
        nullptr, qkv2, PA, MROWS, 1024, 1024, F_LORA | F_PACK);
    pack_launch(ca_kv_w, wcakv2, 2 * PC);
    pack_lora_k<<<MROWS, 256>>>(feature, f2, PA, ca_kv_a, t);
    gemm_fp16<<<dim3(16, 32), 256, GEMM_SMEM>>>(
        f2, PA, wcakv2, ca_kv_b, t, ca_kv_lb,
        nullptr, kv2, 2 * PA, MROWS, 2048, 1024, F_LORA | F_PACK);
    attn_k  <<<dim3(16, 64), 128, ATTN_SMEM>>>(
        qkv2, 1024, PA, kv2, 2048, 2 * PA, kv2 + 1024, 2048, 2 * PA, o2);
    lora_tp_k<<<MROWS, 256>>>(o2, ca_pr_a, t);
    pack_launch(ca_pr_w, wcap2, PC);
    gemm_fp16<<<dim3(8, 32), 256, GEMM_SMEM>>>(
        o2, PA, wcap2, ca_pr_b, t, ca_pr_lb,
        xo, xo, 0, MROWS, 1024, 1024, F_LORA | F_RES);

    // ---- MLP ----
    ln_k    <<<MROWS, 256>>>(xo, ln2_g, ln2_b, h2, nullptr, nullptr);
    pack_launch(fc_w, wfc2, 4 * PC);
    gemm_fp16<<<dim3(32, 32), 256, GEMM_SMEM>>>(
        h2, PA, wfc2, fc_b, nullptr, nullptr,
        nullptr, mlp2, 4 * PA, MROWS, 4096, 1024, F_GELU | F_PACK);
    pack_launch(pr_w, wpr2, 4 * PC);
    gemm_fp16<<<dim3(8, 32), 256, GEMM_SMEM>>>(
        mlp2, 4 * PA, wpr2, pr_b, nullptr, nullptr,
        xo, xo, 0, MROWS, 1024, 4096, F_RES);
}

// round 16
// speedup vs baseline: 2.7954x; 1.3766x over previous
#include <cuda_runtime.h>
#include <cuda_fp16.h>
#include <cstdint>

// ================= scratch (device globals; allocation-free) ==================
#define MROWS 4096
#define CDIM  1024

__device__ float g_t  [MROWS * 16];
__device__ unsigned short g_h2  [(size_t)2 * MROWS * CDIM];
__device__ unsigned short g_o2  [(size_t)2 * MROWS * CDIM];
__device__ unsigned short g_f2  [(size_t)2 * MROWS * CDIM];
__device__ unsigned short g_qkv2[(size_t)2 * MROWS * 3 * CDIM];
__device__ unsigned short g_kv2 [(size_t)2 * MROWS * 2 * CDIM];
__device__ unsigned short g_mlp2[(size_t)2 * MROWS * 4 * CDIM];
__device__ unsigned short g_wqkv2 [(size_t)3 * CDIM * CDIM];
__device__ unsigned short g_wsap2 [(size_t)CDIM * CDIM];
__device__ unsigned short g_wcaq2 [(size_t)CDIM * CDIM];
__device__ unsigned short g_wcakv2[(size_t)2 * CDIM * CDIM];
__device__ unsigned short g_wcap2 [(size_t)CDIM * CDIM];
__device__ unsigned short g_wfc2  [(size_t)4 * CDIM * CDIM];
__device__ unsigned short g_wpr2  [(size_t)CDIM * 4 * CDIM];

static const int F_LORA = 1, F_GELU = 2, F_RES = 4, F_PACK = 8;

// ================= helpers ====================================================
__device__ __forceinline__ uint32_t smem_u32(const void* p) {
    uint32_t a;
    asm("{ .reg .u64 t; cvta.to.shared.u64 t, %1; cvt.u32.u64 %0, t; }"
        : "=r"(a) : "l"(p));
    return a;
}
__device__ __forceinline__ void ldmatrix_x4(uint32_t* r, uint32_t addr) {
    asm volatile("ldmatrix.sync.aligned.m8n8.x4.shared.b16 {%0,%1,%2,%3}, [%4];"
        : "=r"(r[0]), "=r"(r[1]), "=r"(r[2]), "=r"(r[3]) : "r"(addr));
}
__device__ __forceinline__ void ldmatrix_x4_t(uint32_t* r, uint32_t addr) {
    asm volatile("ldmatrix.sync.aligned.m8n8.x4.trans.shared.b16 {%0,%1,%2,%3}, [%4];"
        : "=r"(r[0]), "=r"(r[1]), "=r"(r[2]), "=r"(r[3]) : "r"(addr));
}
__device__ __forceinline__ void mma16816(float* c, const uint32_t* a,
                                         uint32_t b0, uint32_t b1) {
    asm volatile("mma.sync.aligned.m16n8k16.row.col.f32.f16.f16.f32 "
        "{%0,%1,%2,%3}, {%4,%5,%6,%7}, {%8,%9}, {%0,%1,%2,%3};"
        : "+f"(c[0]), "+f"(c[1]), "+f"(c[2]), "+f"(c[3])
        : "r"(a[0]), "r"(a[1]), "r"(a[2]), "r"(a[3]), "r"(b0), "r"(b1));
}
__device__ __forceinline__ uint32_t pack2hi(float a, float b) {
    return (uint32_t)__half_as_ushort(__float2half(a))
         | ((uint32_t)__half_as_ushort(__float2half(b)) << 16);
}
__device__ __forceinline__ uint32_t pack2lo(float a, float b) {
    float ra = a - __half2float(__float2half(a));
    float rb = b - __half2float(__float2half(b));
    return (uint32_t)__half_as_ushort(__float2half(ra))
         | ((uint32_t)__half_as_ushort(__float2half(rb)) << 16);
}
__device__ __forceinline__ float up2f(unsigned short u) {
    return __half2float(__ushort_as_half(u));
}
#define CP_ASYNC16(dst, src) \
    asm volatile("cp.async.cg.shared.global [%0], [%1], 16;" \
        :: "r"(dst), "l"(src) : "memory")
#define CP_COMMIT() asm volatile("cp.async.commit_group;" ::: "memory")

// ================= pack (hi+lo planes, for activations) =======================
__global__ __launch_bounds__(256) void pack_k(const float* __restrict__ X,
                                              unsigned short* __restrict__ Y,
                                              int n8, size_t plane)
{
    int g = blockIdx.x * 256 + threadIdx.x;
    if (g >= n8) return;
    float4 v0 = ((const float4*)X)[g * 2];
    float4 v1 = ((const float4*)X)[g * 2 + 1];
    uint4 hi, lo;
    hi.x = pack2hi(v0.x, v0.y); lo.x = pack2lo(v0.x, v0.y);
    hi.y = pack2hi(v0.z, v0.w); lo.y = pack2lo(v0.z, v0.w);
    hi.z = pack2hi(v1.x, v1.y); lo.z = pack2lo(v1.x, v1.y);
    hi.w = pack2hi(v1.z, v1.w); lo.w = pack2lo(v1.z, v1.w);
    *(uint4*)(Y + (size_t)g * 8)         = hi;
    *(uint4*)(Y + plane + (size_t)g * 8) = lo;
}

// ================= pack weights (hi plane only) ===============================
__global__ __launch_bounds__(256) void packw_k(const float* __restrict__ X,
                                               unsigned short* __restrict__ Y,
                                               int n8)
{
    int g = blockIdx.x * 256 + threadIdx.x;
    if (g >= n8) return;
    float4 v0 = ((const float4*)X)[g * 2];
    float4 v1 = ((const float4*)X)[g * 2 + 1];
    uint4 hi;
    hi.x = pack2hi(v0.x, v0.y);
    hi.y = pack2hi(v0.z, v0.w);
    hi.z = pack2hi(v1.x, v1.y);
    hi.w = pack2hi(v1.z, v1.w);
    *(uint4*)(Y + (size_t)g * 8) = hi;
}

// ======= pack rows + fused lora t = x @ A^T (one block per row) ===============
__global__ __launch_bounds__(256) void pack_lora_k(const float* __restrict__ X,
                                                   unsigned short* __restrict__ Y,
                                                   size_t plane,
                                                   const float* __restrict__ Aw,
                                                   float* __restrict__ T)
{
    const int row = blockIdx.x, t = threadIdx.x;
    const float* xr = X + (size_t)row * 1024;
    float4 v = ((const float4*)xr)[t];
    *(uint2*)(Y + (size_t)row * 1024 + t * 4) =
        make_uint2(pack2hi(v.x, v.y), pack2hi(v.z, v.w));
    *(uint2*)(Y + plane + (size_t)row * 1024 + t * 4) =
        make_uint2(pack2lo(v.x, v.y), pack2lo(v.z, v.w));

    __shared__ float lred[8][16];
    const int lane = t & 31, warp = t >> 5;
    float acc[16];
#pragma unroll
    for (int r = 0; r < 16; r++) {
        float4 av = *(const float4*)&Aw[r * 1024 + t * 4];
        acc[r] = v.x * av.x + v.y * av.y + v.z * av.z + v.w * av.w;
    }
#pragma unroll
    for (int r = 0; r < 16; r++) {
        float vv = acc[r];
#pragma unroll
        for (int o = 16; o > 0; o >>= 1)
            vv += __shfl_down_sync(0xffffffffu, vv, o);
        if (lane == 0) lred[warp][r] = vv;
    }
    __syncthreads();
    if (t < 16) {
        float s = 0.f;
#pragma unroll
        for (int w = 0; w < 8; w++) s += lred[w][t];
        T[(size_t)row * 16 + t] = s;
    }
}

// ====== LayerNorm -> packed planes, with optional fused lora t = y @ A^T ======
__global__ __launch_bounds__(256) void ln_k(const float* __restrict__ X,
                                            const float* __restrict__ gw,
                                            const float* __restrict__ bw,
                                            unsigned short* __restrict__ O2,
                                            const float* __restrict__ Aw,
                                            float* __restrict__ T)
{
    const size_t PL = (size_t)MROWS * CDIM;
    const int row = blockIdx.x, t = threadIdx.x;
    const float* xr = X + (size_t)row * 1024;
    float4 v = ((const float4*)xr)[t];
    float loc[4] = {v.x, v.y, v.z, v.w};
    float sum = loc[0] + loc[1] + loc[2] + loc[3];
    __shared__ float red[256];
    __shared__ float lred[8][16];
    red[t] = sum; __syncthreads();
#pragma unroll
    for (int o = 128; o > 0; o >>= 1) { if (t < o) red[t] += red[t + o]; __syncthreads(); }
    const float mean = red[0] * (1.f / 1024.f);
    __syncthreads();
    float vs = 0.f;
#pragma unroll
    for (int i = 0; i < 4; i++) { float d = loc[i] - mean; vs += d * d; }
    red[t] = vs; __syncthreads();
#pragma unroll
    for (int o = 128; o > 0; o >>= 1) { if (t < o) red[t] += red[t + o]; __syncthreads(); }
    const float inv = rsqrtf(red[0] * (1.f / 1024.f) + 1e-5f);
    float4 gv = ((const float4*)gw)[t];
    float4 bv = ((const float4*)bw)[t];
    float y[4];
    y[0] = (loc[0] - mean) * inv * gv.x + bv.x;
    y[1] = (loc[1] - mean) * inv * gv.y + bv.y;
    y[2] = (loc[2] - mean) * inv * gv.z + bv.z;
    y[3] = (loc[3] - mean) * inv * gv.w + bv.w;
    *(uint2*)(O2 + (size_t)row * 1024 + t * 4) =
        make_uint2(pack2hi(y[0], y[1]), pack2hi(y[2], y[3]));
    *(uint2*)(O2 + PL + (size_t)row * 1024 + t * 4) =
        make_uint2(pack2lo(y[0], y[1]), pack2lo(y[2], y[3]));

    if (Aw != nullptr) {
        const int lane = t & 31, warp = t >> 5;
        float acc[16];
#pragma unroll
        for (int r = 0; r < 16; r++) {
            float4 av = *(const float4*)&Aw[r * 1024 + t * 4];
            acc[r] = y[0] * av.x + y[1] * av.y + y[2] * av.z + y[3] * av.w;
        }
#pragma unroll
        for (int r = 0; r < 16; r++) {
            float vv = acc[r];
#pragma unroll
            for (int o = 16; o > 0; o >>= 1)
                vv += __shfl_down_sync(0xffffffffu, vv, o);
            if (lane == 0) lred[warp][r] = vv;
        }
        __syncthreads();
        if (t < 16) {
            float s = 0.f;
#pragma unroll
            for (int w = 0; w < 8; w++) s += lred[w][t];
            T[(size_t)row * 16 + t] = s;
        }
    }
}

// ================= lora t: packed hi/lo input variant =========================
__global__ __launch_bounds__(256) void lora_tp_k(const unsigned short* __restrict__ X2,
                                                 const float* __restrict__ Aw,
                                                 float* __restrict__ T)
{
    const size_t PL = (size_t)MROWS * CDIM;
    const int row = blockIdx.x;
    const unsigned short* xh = X2 + (size_t)row * 1024;
    const unsigned short* xl = xh + PL;
    float acc[16];
#pragma unroll
    for (int r = 0; r < 16; r++) acc[r] = 0.f;
    for (int k = threadIdx.x; k < 1024; k += 256) {
        float xv = up2f(xh[k]) + up2f(xl[k]);
#pragma unroll
        for (int r = 0; r < 16; r++) acc[r] += xv * Aw[r * 1024 + k];
    }
    __shared__ float red[8][16];
    const int lane = threadIdx.x & 31, warp = threadIdx.x >> 5;
#pragma unroll
    for (int r = 0; r < 16; r++) {
        float v = acc[r];
#pragma unroll
        for (int o = 16; o > 0; o >>= 1) v += __shfl_down_sync(0xffffffffu, v, o);
        if (lane == 0) red[warp][r] = v;
    }
    __syncthreads();
    if (threadIdx.x < 16) {
        float s = 0.f;
#pragma unroll
        for (int w = 0; w < 8; w++) s += red[w][threadIdx.x];
        T[(size_t)row * 16 + threadIdx.x] = s;
    }
}

// ========= fp16 HMMA GEMM, 1-pass (fp16 A-hi x fp16 B-hi), K-chunk 64 =========
#define NSTAGE 3
#define STG_B 32768
#define GEMM_SMEM (NSTAGE * STG_B)

__global__ __launch_bounds__(256, 2) void gemm_fp16(
    const unsigned short* __restrict__ A,
    const unsigned short* __restrict__ B,
    const float* __restrict__ bias,
    const float* __restrict__ lT, const float* __restrict__ lB,
    const float* __restrict__ res,
    void* __restrict__ Cout, size_t cPl,
    int M, int N, int K, int flags)
{
    extern __shared__ char smem[];
    const uint32_t sb0 = smem_u32(smem);
    const int tid = threadIdx.x, lane = tid & 31, wid = tid >> 5;
    const int wm = wid >> 2, wn = wid & 3;
    const int bm = blockIdx.y * 128, bn = blockIdx.x * 128;
    const int NC = K >> 6;

    const int lr = tid & 127, side = tid >> 7;
    const unsigned short* gh = side ? B + (size_t)(bn + lr) * K
                                    : A + (size_t)(bm + lr) * K;
    uint32_t dst[8];
#pragma unroll
    for (int c = 0; c < 8; c++)
        dst[c] = (uint32_t)side * 16384u + (uint32_t)lr * 128u
               + (uint32_t)((c ^ (lr & 7)) << 4);

    float acc[4][4][4];
#pragma unroll
    for (int i = 0; i < 4; i++)
#pragma unroll
        for (int j = 0; j < 4; j++)
#pragma unroll
            for (int q = 0; q < 4; q++) acc[i][j][q] = 0.f;

    auto issue = [&](int s, int kt) {
        uint32_t st = sb0 + s * STG_B;
        const unsigned short* ph = gh + kt * 64;
#pragma unroll
        for (int c = 0; c < 8; c++)
            CP_ASYNC16(st + dst[c], ph + c * 8);
    };

    issue(0, 0); CP_COMMIT();
    issue(1, 1); CP_COMMIT();

    int scur = 0, snext = 2;
    for (int kt = 0; kt < NC; kt++) {
        asm volatile("cp.async.wait_group 1;" ::: "memory");
        __syncthreads();
        if (kt + 2 < NC) { issue(snext, kt + 2); CP_COMMIT();
                           snext = (snext == 2) ? 0 : snext + 1; }

        const uint32_t st = sb0 + scur * STG_B;
        scur = (scur == 2) ? 0 : scur + 1;
#pragma unroll
        for (int ks = 0; ks < 4; ks++) {
            uint32_t ah[4][4];
#pragma unroll
            for (int i = 0; i < 4; i++) {
                const int r = wm * 64 + i * 16 + (lane & 15);
                const int ch = ks * 2 + (lane >> 4);
                ldmatrix_x4(ah[i], st + r * 128 + ((ch ^ (r & 7)) << 4));
            }
#pragma unroll
            for (int jj = 0; jj < 2; jj++) {
                const int r = wn * 32 + jj * 16 + (lane & 7) + ((lane >> 4) << 3);
                const int ch = ks * 2 + ((lane >> 3) & 1);
                uint32_t bh[4];
                ldmatrix_x4(bh, st + 16384 + r * 128 + ((ch ^ (r & 7)) << 4));
#pragma unroll
                for (int i = 0; i < 4; i++) {
                    mma16816(acc[i][2 * jj],     ah[i], bh[0], bh[1]);
                    mma16816(acc[i][2 * jj + 1], ah[i], bh[2], bh[3]);
                }
            }
        }
    }
    asm volatile("cp.async.wait_group 0;" ::: "memory");
    __syncthreads();

    float* sLT = (float*)smem;
    float* sLB = (float*)(smem + 8192);
    if (flags & F_LORA) {
        if (tid < 128) {
#pragma unroll
            for (int q = 0; q < 4; q++)
                ((float4*)&sLT[tid * 16])[q] = ((const float4*)&lT[(size_t)(bm + tid) * 16])[q];
        } else {
            int r = tid - 128;
#pragma unroll
            for (int q = 0; q < 4; q++)
                ((float4*)&sLB[r * 16])[q] = ((const float4*)&lB[(size_t)(bn + r) * 16])[q];
        }
        __syncthreads();
    }

#pragma unroll
    for (int i = 0; i < 4; i++) {
#pragma unroll
        for (int j = 0; j < 4; j++) {
            const int ml = wm * 64 + i * 16 + (lane >> 2);
            const int nl = wn * 32 + j * 8 + (lane & 3) * 2;
            float v[4] = {acc[i][j][0], acc[i][j][1], acc[i][j][2], acc[i][j][3]};
            const float b0 = bias[bn + nl], b1 = bias[bn + nl + 1];
            v[0] += b0; v[1] += b1; v[2] += b0; v[3] += b1;
            if (flags & F_LORA) {
                float s00 = 0, s01 = 0, s10 = 0, s11 = 0;
#pragma unroll
                for (int r = 0; r < 16; r++) {
                    float t0 = sLT[ml * 16 + r], t1 = sLT[(ml + 8) * 16 + r];
                    float u0 = sLB[nl * 16 + r], u1 = sLB[(nl + 1) * 16 + r];
                    s00 += t0 * u0; s01 += t0 * u1; s10 += t1 * u0; s11 += t1 * u1;
                }
                v[0] += s00 * 0.0625f; v[1] += s01 * 0.0625f;
                v[2] += s10 * 0.0625f; v[3] += s11 * 0.0625f;
            }
            if (flags & F_GELU) {
#pragma unroll
                for (int q = 0; q < 4; q++) {
                    float u = v[q];
                    float c2 = 0.7978845608028654f * (u + 0.044715f * u * u * u);
                    v[q] = 0.5f * u * (1.0f + tanhf(c2));
                }
            }
            const int m0 = bm + ml, m1 = m0 + 8, n0 = bn + nl;
            if (flags & F_RES) {
                float2 r0 = *(const float2*)&res[(size_t)m0 * N + n0];
                float2 r1 = *(const float2*)&res[(size_t)m1 * N + n0];
                v[0] += r0.x; v[1] += r0.y; v[2] += r1.x; v[3] += r1.y;
            }
            if (flags & F_PACK) {
                unsigned short* Y = (unsigned short*)Cout;
                *(uint32_t*)(Y + (size_t)m0 * N + n0)       = pack2hi(v[0], v[1]);
                *(uint32_t*)(Y + cPl + (size_t)m0 * N + n0) = pack2lo(v[0], v[1]);
                *(uint32_t*)(Y + (size_t)m1 * N + n0)       = pack2hi(v[2], v[3]);
                *(uint32_t*)(Y + cPl + (size_t)m1 * N + n0) = pack2lo(v[2], v[3]);
            } else {
                float* C = (float*)Cout;
                *(float2*)&C[(size_t)m0 * N + n0] = make_float2(v[0], v[1]);
                *(float2*)&C[(size_t)m1 * N + n0] = make_float2(v[2], v[3]);
            }
        }
    }
}

// == fp16 flash attention, 2-pass (exact Q/P x fp16 K/V), 16KB stages ==========
#define ATTN_SMEM 32768

__global__ __launch_bounds__(128) void attn_k(
    const unsigned short* __restrict__ Qp, int qs, size_t qPl,
    const unsigned short* __restrict__ Kp, int ks,
    const unsigned short* __restrict__ Vp, int vs,
    unsigned short* __restrict__ O2)
{
    extern __shared__ char smem[];
    const uint32_t sb0 = smem_u32(smem);
    const size_t OPL = (size_t)MROWS * CDIM;
    const int qt = gridDim.x - 1 - blockIdx.x;
    const int b = blockIdx.y >> 4, h = blockIdx.y & 15;
    const int tid = threadIdx.x, lane = tid & 31, wm = tid >> 5;
    const size_t rowbase = (size_t)b * 1024;
    const int hoff = h * 64;

    const int r = tid >> 1, cg = (tid & 1) * 4;
    uint32_t dstc[4];
#pragma unroll
    for (int c = 0; c < 4; c++)
        dstc[c] = (uint32_t)r * 128u + (uint32_t)(((cg + c) ^ (r & 7)) << 4);

    {
        const unsigned short* qh = Qp + (rowbase + (size_t)qt * 64 + r) * qs + hoff;
        const unsigned short* ql = qh + qPl;
#pragma unroll
        for (int c = 0; c < 4; c++) {
            CP_ASYNC16(sb0 + dstc[c],        qh + (cg + c) * 8);
            CP_ASYNC16(sb0 + 8192 + dstc[c], ql + (cg + c) * 8);
        }
        CP_COMMIT();
        asm volatile("cp.async.wait_group 0;" ::: "memory");
    }
    __syncthreads();

    uint32_t Qh[4][4], Ql[4][4];
    {
        const int j = lane >> 3, rr2 = lane & 7;
        const int row = wm * 16 + ((j & 1) << 3) + rr2;
#pragma unroll
        for (int kc = 0; kc < 4; kc++) {
            const int col = kc * 16 + ((j >> 1) << 3);
            const uint32_t off = (uint32_t)row * 128 + ((((uint32_t)col >> 3) ^ (row & 7)) << 4);
            ldmatrix_x4(Qh[kc], sb0 + off);
            ldmatrix_x4(Ql[kc], sb0 + 8192 + off);
        }
    }
    __syncthreads();

    auto issue_kv = [&](int stage, int jt) {
        const uint32_t st = sb0 + stage * 16384;
        const size_t grow = rowbase + (size_t)jt * 64 + r;
        const unsigned short* kh = Kp + grow * ks + hoff;
        const unsigned short* vh = Vp + grow * vs + hoff;
#pragma unroll
        for (int c = 0; c < 4; c++) {
            CP_ASYNC16(st + dstc[c],        kh + (cg + c) * 8);
            CP_ASYNC16(st + 8192 + dstc[c], vh + (cg + c) * 8);
        }
    };

    float oacc[8][4];
#pragma unroll
    for (int nt = 0; nt < 8; nt++)
#pragma unroll
        for (int q = 0; q < 4; q++) oacc[nt][q] = 0.f;
    float m0v = -1e30f, m1v = -1e30f, l0 = 0.f, l1 = 0.f;

    const int jj = lane >> 3, rr2 = lane & 7;
    const int nTiles = qt + 1;

    issue_kv(0, 0);
    CP_COMMIT();

    for (int jt = 0; jt < nTiles; jt++) {
        if (jt + 1 < nTiles) { issue_kv((jt + 1) & 1, jt + 1); CP_COMMIT(); }
        if (jt + 1 < nTiles) asm volatile("cp.async.wait_group 1;" ::: "memory");
        else                 asm volatile("cp.async.wait_group 0;" ::: "memory");
        __syncthreads();
        const uint32_t st = sb0 + (jt & 1) * 16384;

        float sacc[8][4];
#pragma unroll
        for (int nt = 0; nt < 8; nt++)
#pragma unroll
            for (int q = 0; q < 4; q++) sacc[nt][q] = 0.f;

#pragma unroll
        for (int kc = 0; kc < 4; kc++) {
#pragma unroll
            for (int p = 0; p < 4; p++) {
                const int krow = p * 16 + ((jj >> 1) << 3) + rr2;
                const int kcol = kc * 16 + ((jj & 1) << 3);
                const uint32_t off = (uint32_t)krow * 128
                                   + ((((uint32_t)kcol >> 3) ^ (krow & 7)) << 4);
                uint32_t bh[4];
                ldmatrix_x4(bh, st + off);
                mma16816(sacc[2*p],   Qh[kc], bh[0], bh[1]);
                mma16816(sacc[2*p+1], Qh[kc], bh[2], bh[3]);
                mma16816(sacc[2*p],   Ql[kc], bh[0], bh[1]);
                mma16816(sacc[2*p+1], Ql[kc], bh[2], bh[3]);
            }
        }
#pragma unroll
        for (int nt = 0; nt < 8; nt++)
#pragma unroll
            for (int q = 0; q < 4; q++) sacc[nt][q] *= 0.125f;

        const int rA = lane >> 2;
        if (jt == qt) {
            const int gA = wm * 16 + rA, gB = gA + 8;
#pragma unroll
            for (int nt = 0; nt < 8; nt++) {
                const int c = nt * 8 + (lane & 3) * 2;
                if (c     > gA) sacc[nt][0] = -1e30f;
                if (c + 1 > gA) sacc[nt][1] = -1e30f;
                if (c     > gB) sacc[nt][2] = -1e30f;
                if (c + 1 > gB) sacc[nt][3] = -1e30f;
            }
        }
        float mxA = -1e30f, mxB = -1e30f;
#pragma unroll
        for (int nt = 0; nt < 8; nt++) {
            mxA = fmaxf(mxA, fmaxf(sacc[nt][0], sacc[nt][1]));
            mxB = fmaxf(mxB, fmaxf(sacc[nt][2], sacc[nt][3]));
        }
        mxA = fmaxf(mxA, __shfl_xor_sync(0xffffffffu, mxA, 1));
        mxA = fmaxf(mxA, __shfl_xor_sync(0xffffffffu, mxA, 2));
        mxB = fmaxf(mxB, __shfl_xor_sync(0xffffffffu, mxB, 1));
        mxB = fmaxf(mxB, __shfl_xor_sync(0xffffffffu, mxB, 2));
        const float mnA = fmaxf(m0v, mxA), mnB = fmaxf(m1v, mxB);
        const float aA = __expf(m0v - mnA), aB = __expf(m1v - mnB);
        float sA = 0.f, sB = 0.f;
#pragma unroll
        for (int nt = 0; nt < 8; nt++) {
            float p0 = __expf(sacc[nt][0] - mnA);
            float p1 = __expf(sacc[nt][1] - mnA);
            float p2 = __expf(sacc[nt][2] - mnB);
            float p3 = __expf(sacc[nt][3] - mnB);
            sacc[nt][0] = p0; sacc[nt][1] = p1; sacc[nt][2] = p2; sacc[nt][3] = p3;
            sA += p0 + p1; sB += p2 + p3;
        }
        sA += __shfl_xor_sync(0xffffffffu, sA, 1);
        sA += __shfl_xor_sync(0xffffffffu, sA, 2);
        sB += __shfl_xor_sync(0xffffffffu, sB, 1);
        sB += __shfl_xor_sync(0xffffffffu, sB, 2);
        l0 = l0 * aA + sA; l1 = l1 * aB + sB;
        m0v = mnA; m1v = mnB;
#pragma unroll
        for (int nt = 0; nt < 8; nt++) {
            oacc[nt][0] *= aA; oacc[nt][1] *= aA;
            oacc[nt][2] *= aB; oacc[nt][3] *= aB;
        }

        uint32_t Ph[4][4], Pl[4][4];
#pragma unroll
        for (int kc = 0; kc < 4; kc++) {
            float* t0 = sacc[2 * kc];
            float* t1 = sacc[2 * kc + 1];
            Ph[kc][0] = pack2hi(t0[0], t0[1]); Pl[kc][0] = pack2lo(t0[0], t0[1]);
            Ph[kc][1] = pack2hi(t0[2], t0[3]); Pl[kc][1] = pack2lo(t0[2], t0[3]);
            Ph[kc][2] = pack2hi(t1[0], t1[1]); Pl[kc][2] = pack2lo(t1[0], t1[1]);
            Ph[kc][3] = pack2hi(t1[2], t1[3]); Pl[kc][3] = pack2lo(t1[2], t1[3]);
        }

#pragma unroll
        for (int kc = 0; kc < 4; kc++) {
            const int vrow = kc * 16 + ((jj & 1) << 3) + rr2;
#pragma unroll
            for (int p = 0; p < 4; p++) {
                const int vcol = p * 16 + ((jj >> 1) << 3);
                const uint32_t off = (uint32_t)vrow * 128
                                   + ((((uint32_t)vcol >> 3) ^ (vrow & 7)) << 4);
                uint32_t vh[4];
                ldmatrix_x4_t(vh, st + 8192 + off);
                mma16816(oacc[2*p],   Ph[kc], vh[0], vh[1]);
                mma16816(oacc[2*p+1], Ph[kc], vh[2], vh[3]);
                mma16816(oacc[2*p],   Pl[kc], vh[0], vh[1]);
                mma16816(oacc[2*p+1], Pl[kc], vh[2], vh[3]);
            }
        }
        __syncthreads();
    }

    const float iA = 1.f / l0, iB = 1.f / l1;
    const int rA = lane >> 2;
    const size_t grA = (rowbase + (size_t)qt * 64 + wm * 16 + rA) * 1024 + hoff;
    const size_t grB = grA + 8 * 1024;
#pragma unroll
    for (int nt = 0; nt < 8; nt++) {
        const int c = nt * 8 + (lane & 3) * 2;
        float a0 = oacc[nt][0] * iA, a1 = oacc[nt][1] * iA;
        float b0 = oacc[nt][2] * iB, b1 = oacc[nt][3] * iB;
        *(uint32_t*)(O2 + grA + c)       = pack2hi(a0, a1);
        *(uint32_t*)(O2 + OPL + grA + c) = pack2lo(a0, a1);
        *(uint32_t*)(O2 + grB + c)       = pack2hi(b0, b1);
        *(uint32_t*)(O2 + OPL + grB + c) = pack2lo(b0, b1);
    }
}

// ================= host orchestration =========================================
static inline void pack_launch(const float* src, unsigned short* dst, size_t nelem) {
    int n8 = (int)(nelem / 8);
    pack_k<<<(n8 + 255) / 256, 256>>>(src, dst, n8, nelem);
}
static inline void packw_launch(const float* src, unsigned short* dst, size_t nelem) {
    int n8 = (int)(nelem / 8);
    packw_k<<<(n8 + 255) / 256, 256>>>(src, dst, n8);
}

extern "C" void kernel_launch(void* const* d_in, const int* in_sizes, int n_in,
                              void* d_out, int out_size)
{
    const float* x        = (const float*)d_in[0];
    const float* feature  = (const float*)d_in[1];
    const float* ln1_g    = (const float*)d_in[2];
    const float* ln1_b    = (const float*)d_in[3];
    const float* ln2_g    = (const float*)d_in[4];
    const float* ln2_b    = (const float*)d_in[5];
    const float* sa_qkv_w = (const float*)d_in[6];
    const float* sa_qkv_b = (const float*)d_in[7];
    const float* sa_qkv_a = (const float*)d_in[8];
    const float* sa_qkv_lb= (const float*)d_in[9];
    const float* sa_pr_w  = (const float*)d_in[10];
    const float* sa_pr_b  = (const float*)d_in[11];
    const float* sa_pr_a  = (const float*)d_in[12];
    const float* sa_pr_lb = (const float*)d_in[13];
    const float* ca_q_w   = (const float*)d_in[14];
    const float* ca_q_b   = (const float*)d_in[15];
    const float* ca_q_a   = (const float*)d_in[16];
    const float* ca_q_lb  = (const float*)d_in[17];
    const float* ca_kv_w  = (const float*)d_in[18];
    const float* ca_kv_b  = (const float*)d_in[19];
    const float* ca_kv_a  = (const float*)d_in[20];
    const float* ca_kv_lb = (const float*)d_in[21];
    const float* ca_pr_w  = (const float*)d_in[22];
    const float* ca_pr_b  = (const float*)d_in[23];
    const float* ca_pr_a  = (const float*)d_in[24];
    const float* ca_pr_lb = (const float*)d_in[25];
    const float* fc_w     = (const float*)d_in[26];
    const float* fc_b     = (const float*)d_in[27];
    const float* pr_w     = (const float*)d_in[28];
    const float* pr_b     = (const float*)d_in[29];

    float* xo = (float*)d_out;

    float* t;
    unsigned short *h2, *o2, *f2, *qkv2, *kv2, *mlp2;
    unsigned short *wqkv2, *wsap2, *wcaq2, *wcakv2, *wcap2, *wfc2, *wpr2;
    cudaGetSymbolAddress((void**)&t,     g_t);
    cudaGetSymbolAddress((void**)&h2,    g_h2);
    cudaGetSymbolAddress((void**)&o2,    g_o2);
    cudaGetSymbolAddress((void**)&f2,    g_f2);
    cudaGetSymbolAddress((void**)&qkv2,  g_qkv2);
    cudaGetSymbolAddress((void**)&kv2,   g_kv2);
    cudaGetSymbolAddress((void**)&mlp2,  g_mlp2);
    cudaGetSymbolAddress((void**)&wqkv2, g_wqkv2);
    cudaGetSymbolAddress((void**)&wsap2, g_wsap2);
    cudaGetSymbolAddress((void**)&wcaq2, g_wcaq2);
    cudaGetSymbolAddress((void**)&wcakv2,g_wcakv2);
    cudaGetSymbolAddress((void**)&wcap2, g_wcap2);
    cudaGetSymbolAddress((void**)&wfc2,  g_wfc2);
    cudaGetSymbolAddress((void**)&wpr2,  g_wpr2);

    cudaFuncSetAttribute(gemm_fp16, cudaFuncAttributeMaxDynamicSharedMemorySize,
                         GEMM_SMEM);
    cudaFuncSetAttribute(attn_k, cudaFuncAttributeMaxDynamicSharedMemorySize,
                         ATTN_SMEM);

    cudaMemcpyAsync(xo, x, (size_t)MROWS * CDIM * sizeof(float),
                    cudaMemcpyDeviceToDevice);

    const size_t PC = (size_t)CDIM * CDIM;
    const size_t PA = (size_t)MROWS * CDIM;

    // ---- self attention ----
    packw_launch(sa_qkv_w, wqkv2, 3 * PC);
    ln_k    <<<MROWS, 256>>>(xo, ln1_g, ln1_b, h2, sa_qkv_a, t);
    gemm_fp16<<<dim3(24, 32), 256, GEMM_SMEM>>>(
        h2, wqkv2, sa_qkv_b, t, sa_qkv_lb,
        nullptr, qkv2, 3 * PA, MROWS, 3072, 1024, F_LORA | F_PACK);
    attn_k  <<<dim3(16, 64), 128, ATTN_SMEM>>>(
        qkv2, 3072, 3 * PA, qkv2 + 1024, 3072, qkv2 + 2048, 3072, o2);
    packw_launch(sa_pr_w, wsap2, PC);
    lora_tp_k<<<MROWS, 256>>>(o2, sa_pr_a, t);
    gemm_fp16<<<dim3(8, 32), 256, GEMM_SMEM>>>(
        o2, wsap2, sa_pr_b, t, sa_pr_lb,
        xo, xo, 0, MROWS, 1024, 1024, F_LORA | F_RES);

    // ---- cross attention (tri(T,S) == causal since T==S) ----
    ln_k    <<<MROWS, 256>>>(xo, ln1_g, ln1_b, h2, ca_q_a, t);
    packw_launch(ca_q_w, wcaq2, PC);
    gemm_fp16<<<dim3(8, 32), 256, GEMM_SMEM>>>(
        h2, wcaq2, ca_q_b, t, ca_q_lb,
        nullptr, qkv2, PA, MROWS, 1024, 1024, F_LORA | F_PACK);
    packw_launch(ca_kv_w, wcakv2, 2 * PC);
    pack_lora_k<<<MROWS, 256>>>(feature, f2, PA, ca_kv_a, t);
    gemm_fp16<<<dim3(16, 32), 256, GEMM_SMEM>>>(
        f2, wcakv2, ca_kv_b, t, ca_kv_lb,
        nullptr, kv2, 2 * PA, MROWS, 2048, 1024, F_LORA | F_PACK);
    attn_k  <<<dim3(16, 64), 128, ATTN_SMEM>>>(
        qkv2, 1024, PA, kv2, 2048, kv2 + 1024, 2048, o2);
    lora_tp_k<<<MROWS, 256>>>(o2, ca_pr_a, t);
    packw_launch(ca_pr_w, wcap2, PC);
    gemm_fp16<<<dim3(8, 32), 256, GEMM_SMEM>>>(
        o2, wcap2, ca_pr_b, t, ca_pr_lb,
        xo, xo, 0, MROWS, 1024, 1024, F_LORA | F_RES);

    // ---- MLP ----
    ln_k    <<<MROWS, 256>>>(xo, ln2_g, ln2_b, h2, nullptr, nullptr);
    packw_launch(fc_w, wfc2, 4 * PC);
    gemm_fp16<<<dim3(32, 32), 256, GEMM_SMEM>>>(
        h2, wfc2, fc_b, nullptr, nullptr,
        nullptr, mlp2, 4 * PA, MROWS, 4096, 1024, F_GELU | F_PACK);
    packw_launch(pr_w, wpr2, 4 * PC);
    gemm_fp16<<<dim3(8, 32), 256, GEMM_SMEM>>>(
        mlp2, wpr2, pr_b, nullptr, nullptr,
        xo, xo, 0, MROWS, 1024, 4096, F_RES);
}

// round 17
// speedup vs baseline: 3.0040x; 1.0746x over previous
#include <cuda_runtime.h>
#include <cuda_fp16.h>
#include <cstdint>

// ================= scratch (device globals; allocation-free) ==================
#define MROWS 4096
#define CDIM  1024

__device__ float g_t  [MROWS * 16];
__device__ unsigned short g_h2  [(size_t)MROWS * CDIM];
__device__ unsigned short g_o2  [(size_t)MROWS * CDIM];
__device__ unsigned short g_f2  [(size_t)MROWS * CDIM];
__device__ unsigned short g_qkv2[(size_t)MROWS * 3 * CDIM];
__device__ unsigned short g_kv2 [(size_t)MROWS * 2 * CDIM];
__device__ unsigned short g_mlp2[(size_t)MROWS * 4 * CDIM];
__device__ unsigned short g_wqkv2 [(size_t)3 * CDIM * CDIM];
__device__ unsigned short g_wsap2 [(size_t)CDIM * CDIM];
__device__ unsigned short g_wcaq2 [(size_t)CDIM * CDIM];
__device__ unsigned short g_wcakv2[(size_t)2 * CDIM * CDIM];
__device__ unsigned short g_wcap2 [(size_t)CDIM * CDIM];
__device__ unsigned short g_wfc2  [(size_t)4 * CDIM * CDIM];
__device__ unsigned short g_wpr2  [(size_t)CDIM * 4 * CDIM];

static const int F_LORA = 1, F_GELU = 2, F_RES = 4, F_PACK = 8;

// ================= helpers ====================================================
__device__ __forceinline__ uint32_t smem_u32(const void* p) {
    uint32_t a;
    asm("{ .reg .u64 t; cvta.to.shared.u64 t, %1; cvt.u32.u64 %0, t; }"
        : "=r"(a) : "l"(p));
    return a;
}
__device__ __forceinline__ void ldmatrix_x4(uint32_t* r, uint32_t addr) {
    asm volatile("ldmatrix.sync.aligned.m8n8.x4.shared.b16 {%0,%1,%2,%3}, [%4];"
        : "=r"(r[0]), "=r"(r[1]), "=r"(r[2]), "=r"(r[3]) : "r"(addr));
}
__device__ __forceinline__ void ldmatrix_x4_t(uint32_t* r, uint32_t addr) {
    asm volatile("ldmatrix.sync.aligned.m8n8.x4.trans.shared.b16 {%0,%1,%2,%3}, [%4];"
        : "=r"(r[0]), "=r"(r[1]), "=r"(r[2]), "=r"(r[3]) : "r"(addr));
}
__device__ __forceinline__ void mma16816(float* c, const uint32_t* a,
                                         uint32_t b0, uint32_t b1) {
    asm volatile("mma.sync.aligned.m16n8k16.row.col.f32.f16.f16.f32 "
        "{%0,%1,%2,%3}, {%4,%5,%6,%7}, {%8,%9}, {%0,%1,%2,%3};"
        : "+f"(c[0]), "+f"(c[1]), "+f"(c[2]), "+f"(c[3])
        : "r"(a[0]), "r"(a[1]), "r"(a[2]), "r"(a[3]), "r"(b0), "r"(b1));
}
__device__ __forceinline__ uint32_t pack2hi(float a, float b) {
    return (uint32_t)__half_as_ushort(__float2half(a))
         | ((uint32_t)__half_as_ushort(__float2half(b)) << 16);
}
__device__ __forceinline__ float up2f(unsigned short u) {
    return __half2float(__ushort_as_half(u));
}
#define CP_ASYNC16(dst, src) \
    asm volatile("cp.async.cg.shared.global [%0], [%1], 16;" \
        :: "r"(dst), "l"(src) : "memory")
#define CP_COMMIT() asm volatile("cp.async.commit_group;" ::: "memory")

// ================= pack weights / tensors (hi plane only) =====================
__global__ __launch_bounds__(256) void packw_k(const float* __restrict__ X,
                                               unsigned short* __restrict__ Y,
                                               int n8)
{
    int g = blockIdx.x * 256 + threadIdx.x;
    if (g >= n8) return;
    float4 v0 = ((const float4*)X)[g * 2];
    float4 v1 = ((const float4*)X)[g * 2 + 1];
    uint4 hi;
    hi.x = pack2hi(v0.x, v0.y);
    hi.y = pack2hi(v0.z, v0.w);
    hi.z = pack2hi(v1.x, v1.y);
    hi.w = pack2hi(v1.z, v1.w);
    *(uint4*)(Y + (size_t)g * 8) = hi;
}

// ======= pack rows (hi) + fused lora t = x @ A^T (one block per row) ==========
__global__ __launch_bounds__(256) void pack_lora_k(const float* __restrict__ X,
                                                   unsigned short* __restrict__ Y,
                                                   const float* __restrict__ Aw,
                                                   float* __restrict__ T)
{
    const int row = blockIdx.x, t = threadIdx.x;
    const float* xr = X + (size_t)row * 1024;
    float4 v = ((const float4*)xr)[t];
    *(uint2*)(Y + (size_t)row * 1024 + t * 4) =
        make_uint2(pack2hi(v.x, v.y), pack2hi(v.z, v.w));

    __shared__ float lred[8][16];
    const int lane = t & 31, warp = t >> 5;
    float acc[16];
#pragma unroll
    for (int r = 0; r < 16; r++) {
        float4 av = *(const float4*)&Aw[r * 1024 + t * 4];
        acc[r] = v.x * av.x + v.y * av.y + v.z * av.z + v.w * av.w;
    }
#pragma unroll
    for (int r = 0; r < 16; r++) {
        float vv = acc[r];
#pragma unroll
        for (int o = 16; o > 0; o >>= 1)
            vv += __shfl_down_sync(0xffffffffu, vv, o);
        if (lane == 0) lred[warp][r] = vv;
    }
    __syncthreads();
    if (t < 16) {
        float s = 0.f;
#pragma unroll
        for (int w = 0; w < 8; w++) s += lred[w][t];
        T[(size_t)row * 16 + t] = s;
    }
}

// ====== LayerNorm -> packed hi, with optional fused lora t = y @ A^T ==========
__global__ __launch_bounds__(256) void ln_k(const float* __restrict__ X,
                                            const float* __restrict__ gw,
                                            const float* __restrict__ bw,
                                            unsigned short* __restrict__ O2,
                                            const float* __restrict__ Aw,
                                            float* __restrict__ T)
{
    const int row = blockIdx.x, t = threadIdx.x;
    const float* xr = X + (size_t)row * 1024;
    float4 v = ((const float4*)xr)[t];
    float loc[4] = {v.x, v.y, v.z, v.w};
    float sum = loc[0] + loc[1] + loc[2] + loc[3];
    __shared__ float red[256];
    __shared__ float lred[8][16];
    red[t] = sum; __syncthreads();
#pragma unroll
    for (int o = 128; o > 0; o >>= 1) { if (t < o) red[t] += red[t + o]; __syncthreads(); }
    const float mean = red[0] * (1.f / 1024.f);
    __syncthreads();
    float vs = 0.f;
#pragma unroll
    for (int i = 0; i < 4; i++) { float d = loc[i] - mean; vs += d * d; }
    red[t] = vs; __syncthreads();
#pragma unroll
    for (int o = 128; o > 0; o >>= 1) { if (t < o) red[t] += red[t + o]; __syncthreads(); }
    const float inv = rsqrtf(red[0] * (1.f / 1024.f) + 1e-5f);
    float4 gv = ((const float4*)gw)[t];
    float4 bv = ((const float4*)bw)[t];
    float y[4];
    y[0] = (loc[0] - mean) * inv * gv.x + bv.x;
    y[1] = (loc[1] - mean) * inv * gv.y + bv.y;
    y[2] = (loc[2] - mean) * inv * gv.z + bv.z;
    y[3] = (loc[3] - mean) * inv * gv.w + bv.w;
    *(uint2*)(O2 + (size_t)row * 1024 + t * 4) =
        make_uint2(pack2hi(y[0], y[1]), pack2hi(y[2], y[3]));

    if (Aw != nullptr) {
        const int lane = t & 31, warp = t >> 5;
        float acc[16];
#pragma unroll
        for (int r = 0; r < 16; r++) {
            float4 av = *(const float4*)&Aw[r * 1024 + t * 4];
            acc[r] = y[0] * av.x + y[1] * av.y + y[2] * av.z + y[3] * av.w;
        }
#pragma unroll
        for (int r = 0; r < 16; r++) {
            float vv = acc[r];
#pragma unroll
            for (int o = 16; o > 0; o >>= 1)
                vv += __shfl_down_sync(0xffffffffu, vv, o);
            if (lane == 0) lred[warp][r] = vv;
        }
        __syncthreads();
        if (t < 16) {
            float s = 0.f;
#pragma unroll
            for (int w = 0; w < 8; w++) s += lred[w][t];
            T[(size_t)row * 16 + t] = s;
        }
    }
}

// ================= lora t: packed hi input =====================================
__global__ __launch_bounds__(256) void lora_tp_k(const unsigned short* __restrict__ X2,
                                                 const float* __restrict__ Aw,
                                                 float* __restrict__ T)
{
    const int row = blockIdx.x;
    const unsigned short* xh = X2 + (size_t)row * 1024;
    float acc[16];
#pragma unroll
    for (int r = 0; r < 16; r++) acc[r] = 0.f;
    for (int k = threadIdx.x; k < 1024; k += 256) {
        float xv = up2f(xh[k]);
#pragma unroll
        for (int r = 0; r < 16; r++) acc[r] += xv * Aw[r * 1024 + k];
    }
    __shared__ float red[8][16];
    const int lane = threadIdx.x & 31, warp = threadIdx.x >> 5;
#pragma unroll
    for (int r = 0; r < 16; r++) {
        float v = acc[r];
#pragma unroll
        for (int o = 16; o > 0; o >>= 1) v += __shfl_down_sync(0xffffffffu, v, o);
        if (lane == 0) red[warp][r] = v;
    }
    __syncthreads();
    if (threadIdx.x < 16) {
        float s = 0.f;
#pragma unroll
        for (int w = 0; w < 8; w++) s += red[w][threadIdx.x];
        T[(size_t)row * 16 + threadIdx.x] = s;
    }
}

// ========= fp16 HMMA GEMM, 1-pass, K-chunk 64 (R16 config) ====================
#define NSTAGE 3
#define STG_B 32768
#define GEMM_SMEM (NSTAGE * STG_B)

__global__ __launch_bounds__(256, 2) void gemm_fp16(
    const unsigned short* __restrict__ A,
    const unsigned short* __restrict__ B,
    const float* __restrict__ bias,
    const float* __restrict__ lT, const float* __restrict__ lB,
    const float* __restrict__ res,
    void* __restrict__ Cout,
    int M, int N, int K, int flags)
{
    extern __shared__ char smem[];
    const uint32_t sb0 = smem_u32(smem);
    const int tid = threadIdx.x, lane = tid & 31, wid = tid >> 5;
    const int wm = wid >> 2, wn = wid & 3;
    const int bm = blockIdx.y * 128, bn = blockIdx.x * 128;
    const int NC = K >> 6;

    const int lr = tid & 127, side = tid >> 7;
    const unsigned short* gh = side ? B + (size_t)(bn + lr) * K
                                    : A + (size_t)(bm + lr) * K;
    uint32_t dst[8];
#pragma unroll
    for (int c = 0; c < 8; c++)
        dst[c] = (uint32_t)side * 16384u + (uint32_t)lr * 128u
               + (uint32_t)((c ^ (lr & 7)) << 4);

    float acc[4][4][4];
#pragma unroll
    for (int i = 0; i < 4; i++)
#pragma unroll
        for (int j = 0; j < 4; j++)
#pragma unroll
            for (int q = 0; q < 4; q++) acc[i][j][q] = 0.f;

    auto issue = [&](int s, int kt) {
        uint32_t st = sb0 + s * STG_B;
        const unsigned short* ph = gh + kt * 64;
#pragma unroll
        for (int c = 0; c < 8; c++)
            CP_ASYNC16(st + dst[c], ph + c * 8);
    };

    issue(0, 0); CP_COMMIT();
    issue(1, 1); CP_COMMIT();

    int scur = 0, snext = 2;
    for (int kt = 0; kt < NC; kt++) {
        asm volatile("cp.async.wait_group 1;" ::: "memory");
        __syncthreads();
        if (kt + 2 < NC) { issue(snext, kt + 2); CP_COMMIT();
                           snext = (snext == 2) ? 0 : snext + 1; }

        const uint32_t st = sb0 + scur * STG_B;
        scur = (scur == 2) ? 0 : scur + 1;
#pragma unroll
        for (int ks = 0; ks < 4; ks++) {
            uint32_t ah[4][4];
#pragma unroll
            for (int i = 0; i < 4; i++) {
                const int r = wm * 64 + i * 16 + (lane & 15);
                const int ch = ks * 2 + (lane >> 4);
                ldmatrix_x4(ah[i], st + r * 128 + ((ch ^ (r & 7)) << 4));
            }
#pragma unroll
            for (int jj = 0; jj < 2; jj++) {
                const int r = wn * 32 + jj * 16 + (lane & 7) + ((lane >> 4) << 3);
                const int ch = ks * 2 + ((lane >> 3) & 1);
                uint32_t bh[4];
                ldmatrix_x4(bh, st + 16384 + r * 128 + ((ch ^ (r & 7)) << 4));
#pragma unroll
                for (int i = 0; i < 4; i++) {
                    mma16816(acc[i][2 * jj],     ah[i], bh[0], bh[1]);
                    mma16816(acc[i][2 * jj + 1], ah[i], bh[2], bh[3]);
                }
            }
        }
    }
    asm volatile("cp.async.wait_group 0;" ::: "memory");
    __syncthreads();

    float* sLT = (float*)smem;
    float* sLB = (float*)(smem + 8192);
    if (flags & F_LORA) {
        if (tid < 128) {
#pragma unroll
            for (int q = 0; q < 4; q++)
                ((float4*)&sLT[tid * 16])[q] = ((const float4*)&lT[(size_t)(bm + tid) * 16])[q];
        } else {
            int r = tid - 128;
#pragma unroll
            for (int q = 0; q < 4; q++)
                ((float4*)&sLB[r * 16])[q] = ((const float4*)&lB[(size_t)(bn + r) * 16])[q];
        }
        __syncthreads();
    }

#pragma unroll
    for (int i = 0; i < 4; i++) {
#pragma unroll
        for (int j = 0; j < 4; j++) {
            const int ml = wm * 64 + i * 16 + (lane >> 2);
            const int nl = wn * 32 + j * 8 + (lane & 3) * 2;
            float v[4] = {acc[i][j][0], acc[i][j][1], acc[i][j][2], acc[i][j][3]};
            const float b0 = bias[bn + nl], b1 = bias[bn + nl + 1];
            v[0] += b0; v[1] += b1; v[2] += b0; v[3] += b1;
            if (flags & F_LORA) {
                float s00 = 0, s01 = 0, s10 = 0, s11 = 0;
#pragma unroll
                for (int r = 0; r < 16; r++) {
                    float t0 = sLT[ml * 16 + r], t1 = sLT[(ml + 8) * 16 + r];
                    float u0 = sLB[nl * 16 + r], u1 = sLB[(nl + 1) * 16 + r];
                    s00 += t0 * u0; s01 += t0 * u1; s10 += t1 * u0; s11 += t1 * u1;
                }
                v[0] += s00 * 0.0625f; v[1] += s01 * 0.0625f;
                v[2] += s10 * 0.0625f; v[3] += s11 * 0.0625f;
            }
            if (flags & F_GELU) {
#pragma unroll
                for (int q = 0; q < 4; q++) {
                    float u = v[q];
                    float c2 = 0.7978845608028654f * (u + 0.044715f * u * u * u);
                    v[q] = 0.5f * u * (1.0f + tanhf(c2));
                }
            }
            const int m0 = bm + ml, m1 = m0 + 8, n0 = bn + nl;
            if (flags & F_RES) {
                float2 r0 = *(const float2*)&res[(size_t)m0 * N + n0];
                float2 r1 = *(const float2*)&res[(size_t)m1 * N + n0];
                v[0] += r0.x; v[1] += r0.y; v[2] += r1.x; v[3] += r1.y;
            }
            if (flags & F_PACK) {
                unsigned short* Y = (unsigned short*)Cout;
                *(uint32_t*)(Y + (size_t)m0 * N + n0) = pack2hi(v[0], v[1]);
                *(uint32_t*)(Y + (size_t)m1 * N + n0) = pack2hi(v[2], v[3]);
            } else {
                float* C = (float*)Cout;
                *(float2*)&C[(size_t)m0 * N + n0] = make_float2(v[0], v[1]);
                *(float2*)&C[(size_t)m1 * N + n0] = make_float2(v[2], v[3]);
            }
        }
    }
}

// ========== fp16 flash attention, fully 1-pass, 16KB stages ===================
#define ATTN_SMEM 32768

__global__ __launch_bounds__(128) void attn_k(
    const unsigned short* __restrict__ Qp, int qs,
    const unsigned short* __restrict__ Kp, int ks,
    const unsigned short* __restrict__ Vp, int vs,
    unsigned short* __restrict__ O2)
{
    extern __shared__ char smem[];
    const uint32_t sb0 = smem_u32(smem);
    const int qt = gridDim.x - 1 - blockIdx.x;
    const int b = blockIdx.y >> 4, h = blockIdx.y & 15;
    const int tid = threadIdx.x, lane = tid & 31, wm = tid >> 5;
    const size_t rowbase = (size_t)b * 1024;
    const int hoff = h * 64;

    const int r = tid >> 1, cg = (tid & 1) * 4;
    uint32_t dstc[4];
#pragma unroll
    for (int c = 0; c < 4; c++)
        dstc[c] = (uint32_t)r * 128u + (uint32_t)(((cg + c) ^ (r & 7)) << 4);

    {
        const unsigned short* qh = Qp + (rowbase + (size_t)qt * 64 + r) * qs + hoff;
#pragma unroll
        for (int c = 0; c < 4; c++)
            CP_ASYNC16(sb0 + dstc[c], qh + (cg + c) * 8);
        CP_COMMIT();
        asm volatile("cp.async.wait_group 0;" ::: "memory");
    }
    __syncthreads();

    uint32_t Qh[4][4];
    {
        const int j = lane >> 3, rr2 = lane & 7;
        const int row = wm * 16 + ((j & 1) << 3) + rr2;
#pragma unroll
        for (int kc = 0; kc < 4; kc++) {
            const int col = kc * 16 + ((j >> 1) << 3);
            const uint32_t off = (uint32_t)row * 128 + ((((uint32_t)col >> 3) ^ (row & 7)) << 4);
            ldmatrix_x4(Qh[kc], sb0 + off);
        }
    }
    __syncthreads();

    auto issue_kv = [&](int stage, int jt) {
        const uint32_t st = sb0 + stage * 16384;
        const size_t grow = rowbase + (size_t)jt * 64 + r;
        const unsigned short* kh = Kp + grow * ks + hoff;
        const unsigned short* vh = Vp + grow * vs + hoff;
#pragma unroll
        for (int c = 0; c < 4; c++) {
            CP_ASYNC16(st + dstc[c],        kh + (cg + c) * 8);
            CP_ASYNC16(st + 8192 + dstc[c], vh + (cg + c) * 8);
        }
    };

    float oacc[8][4];
#pragma unroll
    for (int nt = 0; nt < 8; nt++)
#pragma unroll
        for (int q = 0; q < 4; q++) oacc[nt][q] = 0.f;
    float m0v = -1e30f, m1v = -1e30f, l0 = 0.f, l1 = 0.f;

    const int jj = lane >> 3, rr2 = lane & 7;
    const int nTiles = qt + 1;

    issue_kv(0, 0);
    CP_COMMIT();

    for (int jt = 0; jt < nTiles; jt++) {
        if (jt + 1 < nTiles) { issue_kv((jt + 1) & 1, jt + 1); CP_COMMIT(); }
        if (jt + 1 < nTiles) asm volatile("cp.async.wait_group 1;" ::: "memory");
        else                 asm volatile("cp.async.wait_group 0;" ::: "memory");
        __syncthreads();
        const uint32_t st = sb0 + (jt & 1) * 16384;

        float sacc[8][4];
#pragma unroll
        for (int nt = 0; nt < 8; nt++)
#pragma unroll
            for (int q = 0; q < 4; q++) sacc[nt][q] = 0.f;

#pragma unroll
        for (int kc = 0; kc < 4; kc++) {
#pragma unroll
            for (int p = 0; p < 4; p++) {
                const int krow = p * 16 + ((jj >> 1) << 3) + rr2;
                const int kcol = kc * 16 + ((jj & 1) << 3);
                const uint32_t off = (uint32_t)krow * 128
                                   + ((((uint32_t)kcol >> 3) ^ (krow & 7)) << 4);
                uint32_t bh[4];
                ldmatrix_x4(bh, st + off);
                mma16816(sacc[2*p],   Qh[kc], bh[0], bh[1]);
                mma16816(sacc[2*p+1], Qh[kc], bh[2], bh[3]);
            }
        }
#pragma unroll
        for (int nt = 0; nt < 8; nt++)
#pragma unroll
            for (int q = 0; q < 4; q++) sacc[nt][q] *= 0.125f;

        const int rA = lane >> 2;
        if (jt == qt) {
            const int gA = wm * 16 + rA, gB = gA + 8;
#pragma unroll
            for (int nt = 0; nt < 8; nt++) {
                const int c = nt * 8 + (lane & 3) * 2;
                if (c     > gA) sacc[nt][0] = -1e30f;
                if (c + 1 > gA) sacc[nt][1] = -1e30f;
                if (c     > gB) sacc[nt][2] = -1e30f;
                if (c + 1 > gB) sacc[nt][3] = -1e30f;
            }
        }
        float mxA = -1e30f, mxB = -1e30f;
#pragma unroll
        for (int nt = 0; nt < 8; nt++) {
            mxA = fmaxf(mxA, fmaxf(sacc[nt][0], sacc[nt][1]));
            mxB = fmaxf(mxB, fmaxf(sacc[nt][2], sacc[nt][3]));
        }
        mxA = fmaxf(mxA, __shfl_xor_sync(0xffffffffu, mxA, 1));
        mxA = fmaxf(mxA, __shfl_xor_sync(0xffffffffu, mxA, 2));
        mxB = fmaxf(mxB, __shfl_xor_sync(0xffffffffu, mxB, 1));
        mxB = fmaxf(mxB, __shfl_xor_sync(0xffffffffu, mxB, 2));
        const float mnA = fmaxf(m0v, mxA), mnB = fmaxf(m1v, mxB);
        const float aA = __expf(m0v - mnA), aB = __expf(m1v - mnB);
        float sA = 0.f, sB = 0.f;
#pragma unroll
        for (int nt = 0; nt < 8; nt++) {
            float p0 = __expf(sacc[nt][0] - mnA);
            float p1 = __expf(sacc[nt][1] - mnA);
            float p2 = __expf(sacc[nt][2] - mnB);
            float p3 = __expf(sacc[nt][3] - mnB);
            sacc[nt][0] = p0; sacc[nt][1] = p1; sacc[nt][2] = p2; sacc[nt][3] = p3;
            sA += p0 + p1; sB += p2 + p3;
        }
        sA += __shfl_xor_sync(0xffffffffu, sA, 1);
        sA += __shfl_xor_sync(0xffffffffu, sA, 2);
        sB += __shfl_xor_sync(0xffffffffu, sB, 1);
        sB += __shfl_xor_sync(0xffffffffu, sB, 2);
        l0 = l0 * aA + sA; l1 = l1 * aB + sB;
        m0v = mnA; m1v = mnB;
#pragma unroll
        for (int nt = 0; nt < 8; nt++) {
            oacc[nt][0] *= aA; oacc[nt][1] *= aA;
            oacc[nt][2] *= aB; oacc[nt][3] *= aB;
        }

        uint32_t Ph[4][4];
#pragma unroll
        for (int kc = 0; kc < 4; kc++) {
            float* t0 = sacc[2 * kc];
            float* t1 = sacc[2 * kc + 1];
            Ph[kc][0] = pack2hi(t0[0], t0[1]);
            Ph[kc][1] = pack2hi(t0[2], t0[3]);
            Ph[kc][2] = pack2hi(t1[0], t1[1]);
            Ph[kc][3] = pack2hi(t1[2], t1[3]);
        }

#pragma unroll
        for (int kc = 0; kc < 4; kc++) {
            const int vrow = kc * 16 + ((jj & 1) << 3) + rr2;
#pragma unroll
            for (int p = 0; p < 4; p++) {
                const int vcol = p * 16 + ((jj >> 1) << 3);
                const uint32_t off = (uint32_t)vrow * 128
                                   + ((((uint32_t)vcol >> 3) ^ (vrow & 7)) << 4);
                uint32_t vh[4];
                ldmatrix_x4_t(vh, st + 8192 + off);
                mma16816(oacc[2*p],   Ph[kc], vh[0], vh[1]);
                mma16816(oacc[2*p+1], Ph[kc], vh[2], vh[3]);
            }
        }
        __syncthreads();
    }

    const float iA = 1.f / l0, iB = 1.f / l1;
    const int rA = lane >> 2;
    const size_t grA = (rowbase + (size_t)qt * 64 + wm * 16 + rA) * 1024 + hoff;
    const size_t grB = grA + 8 * 1024;
#pragma unroll
    for (int nt = 0; nt < 8; nt++) {
        const int c = nt * 8 + (lane & 3) * 2;
        *(uint32_t*)(O2 + grA + c) = pack2hi(oacc[nt][0] * iA, oacc[nt][1] * iA);
        *(uint32_t*)(O2 + grB + c) = pack2hi(oacc[nt][2] * iB, oacc[nt][3] * iB);
    }
}

// ================= host orchestration =========================================
static inline void packw_launch(const float* src, unsigned short* dst, size_t nelem) {
    int n8 = (int)(nelem / 8);
    packw_k<<<(n8 + 255) / 256, 256>>>(src, dst, n8);
}

extern "C" void kernel_launch(void* const* d_in, const int* in_sizes, int n_in,
                              void* d_out, int out_size)
{
    const float* x        = (const float*)d_in[0];
    const float* feature  = (const float*)d_in[1];
    const float* ln1_g    = (const float*)d_in[2];
    const float* ln1_b    = (const float*)d_in[3];
    const float* ln2_g    = (const float*)d_in[4];
    const float* ln2_b    = (const float*)d_in[5];
    const float* sa_qkv_w = (const float*)d_in[6];
    const float* sa_qkv_b = (const float*)d_in[7];
    const float* sa_qkv_a = (const float*)d_in[8];
    const float* sa_qkv_lb= (const float*)d_in[9];
    const float* sa_pr_w  = (const float*)d_in[10];
    const float* sa_pr_b  = (const float*)d_in[11];
    const float* sa_pr_a  = (const float*)d_in[12];
    const float* sa_pr_lb = (const float*)d_in[13];
    const float* ca_q_w   = (const float*)d_in[14];
    const float* ca_q_b   = (const float*)d_in[15];
    const float* ca_q_a   = (const float*)d_in[16];
    const float* ca_q_lb  = (const float*)d_in[17];
    const float* ca_kv_w  = (const float*)d_in[18];
    const float* ca_kv_b  = (const float*)d_in[19];
    const float* ca_kv_a  = (const float*)d_in[20];
    const float* ca_kv_lb = (const float*)d_in[21];
    const float* ca_pr_w  = (const float*)d_in[22];
    const float* ca_pr_b  = (const float*)d_in[23];
    const float* ca_pr_a  = (const float*)d_in[24];
    const float* ca_pr_lb = (const float*)d_in[25];
    const float* fc_w     = (const float*)d_in[26];
    const float* fc_b     = (const float*)d_in[27];
    const float* pr_w     = (const float*)d_in[28];
    const float* pr_b     = (const float*)d_in[29];

    float* xo = (float*)d_out;

    float* t;
    unsigned short *h2, *o2, *f2, *qkv2, *kv2, *mlp2;
    unsigned short *wqkv2, *wsap2, *wcaq2, *wcakv2, *wcap2, *wfc2, *wpr2;
    cudaGetSymbolAddress((void**)&t,     g_t);
    cudaGetSymbolAddress((void**)&h2,    g_h2);
    cudaGetSymbolAddress((void**)&o2,    g_o2);
    cudaGetSymbolAddress((void**)&f2,    g_f2);
    cudaGetSymbolAddress((void**)&qkv2,  g_qkv2);
    cudaGetSymbolAddress((void**)&kv2,   g_kv2);
    cudaGetSymbolAddress((void**)&mlp2,  g_mlp2);
    cudaGetSymbolAddress((void**)&wqkv2, g_wqkv2);
    cudaGetSymbolAddress((void**)&wsap2, g_wsap2);
    cudaGetSymbolAddress((void**)&wcaq2, g_wcaq2);
    cudaGetSymbolAddress((void**)&wcakv2,g_wcakv2);
    cudaGetSymbolAddress((void**)&wcap2, g_wcap2);
    cudaGetSymbolAddress((void**)&wfc2,  g_wfc2);
    cudaGetSymbolAddress((void**)&wpr2,  g_wpr2);

    cudaFuncSetAttribute(gemm_fp16, cudaFuncAttributeMaxDynamicSharedMemorySize,
                         GEMM_SMEM);
    cudaFuncSetAttribute(attn_k, cudaFuncAttributeMaxDynamicSharedMemorySize,
                         ATTN_SMEM);

    cudaMemcpyAsync(xo, x, (size_t)MROWS * CDIM * sizeof(float),
                    cudaMemcpyDeviceToDevice);

    const size_t PC = (size_t)CDIM * CDIM;

    // ---- self attention ----
    packw_launch(sa_qkv_w, wqkv2, 3 * PC);
    ln_k    <<<MROWS, 256>>>(xo, ln1_g, ln1_b, h2, sa_qkv_a, t);
    gemm_fp16<<<dim3(24, 32), 256, GEMM_SMEM>>>(
        h2, wqkv2, sa_qkv_b, t, sa_qkv_lb,
        nullptr, qkv2, MROWS, 3072, 1024, F_LORA | F_PACK);
    attn_k  <<<dim3(16, 64), 128, ATTN_SMEM>>>(
        qkv2, 3072, qkv2 + 1024, 3072, qkv2 + 2048, 3072, o2);
    packw_launch(sa_pr_w, wsap2, PC);
    lora_tp_k<<<MROWS, 256>>>(o2, sa_pr_a, t);
    gemm_fp16<<<dim3(8, 32), 256, GEMM_SMEM>>>(
        o2, wsap2, sa_pr_b, t, sa_pr_lb,
        xo, xo, MROWS, 1024, 1024, F_LORA | F_RES);

    // ---- cross attention (tri(T,S) == causal since T==S) ----
    ln_k    <<<MROWS, 256>>>(xo, ln1_g, ln1_b, h2, ca_q_a, t);
    packw_launch(ca_q_w, wcaq2, PC);
    gemm_fp16<<<dim3(8, 32), 256, GEMM_SMEM>>>(
        h2, wcaq2, ca_q_b, t, ca_q_lb,
        nullptr, qkv2, MROWS, 1024, 1024, F_LORA | F_PACK);
    packw_launch(ca_kv_w, wcakv2, 2 * PC);
    pack_lora_k<<<MROWS, 256>>>(feature, f2, ca_kv_a, t);
    gemm_fp16<<<dim3(16, 32), 256, GEMM_SMEM>>>(
        f2, wcakv2, ca_kv_b, t, ca_kv_lb,
        nullptr, kv2, MROWS, 2048, 1024, F_LORA | F_PACK);
    attn_k  <<<dim3(16, 64), 128, ATTN_SMEM>>>(
        qkv2, 1024, kv2, 2048, kv2 + 1024, 2048, o2);
    lora_tp_k<<<MROWS, 256>>>(o2, ca_pr_a, t);
    packw_launch(ca_pr_w, wcap2, PC);
    gemm_fp16<<<dim3(8, 32), 256, GEMM_SMEM>>>(
        o2, wcap2, ca_pr_b, t, ca_pr_lb,
        xo, xo, MROWS, 1024, 1024, F_LORA | F_RES);

    // ---- MLP ----
    ln_k    <<<MROWS, 256>>>(xo, ln2_g, ln2_b, h2, nullptr, nullptr);
    packw_launch(fc_w, wfc2, 4 * PC);
    gemm_fp16<<<dim3(32, 32), 256, GEMM_SMEM>>>(
        h2, wfc2, fc_b, nullptr, nullptr,
        nullptr, mlp2, MROWS, 4096, 1024, F_GELU | F_PACK);
    packw_launch(pr_w, wpr2, 4 * PC);
    gemm_fp16<<<dim3(8, 32), 256, GEMM_SMEM>>>(
        mlp2, wpr2, pr_b, nullptr, nullptr,
        xo, xo, MROWS, 1024, 4096, F_RES);
}